// round 8
// baseline (speedup 1.0000x reference)
#include <cuda_runtime.h>
#include <math.h>

#define NA    21824      // total anchors per image
#define BATCH 8
#define NBINS 8192
#define KTOP  1000
#define SORTN 2048
#define IOU_THR 0.6f
#define SCORE_THR 0.05f

struct InPtrs {
    const float* cls[5];
    const float* cnt[5];
    const float* reg[5];
};

// ---------------- scratch (device globals; no allocation allowed) ----------
__device__ float    g_score[BATCH * NA];
__device__ int      g_cls  [BATCH * NA];
__device__ float4   g_box  [BATCH * NA];

__device__ int      g_top_idx  [BATCH * KTOP];
__device__ float    g_top_score[BATCH * KTOP];
__device__ int      g_top_cls  [BATCH * KTOP];
__device__ float4   g_top_box  [BATCH * KTOP];

__device__ float4   g_nx   [BATCH * KTOP];   // class-offset boxes
__device__ float    g_area [BATCH * KTOP];

__device__ unsigned g_mask [BATCH * KTOP * 32]; // suppression bitmask rows

// Bit-exact replica of XLA:CPU's GenerateVF32Exp (Cephes expf, unfused
// mul/add). Verified bit-exact against the reference in R6.
__device__ __forceinline__ float xla_cpu_expf(float v) {
    float x = fminf(fmaxf(v, -88.3762626647949f), 88.3762626647950f);
    float fx = floorf(__fadd_rn(__fmul_rn(x, 1.44269504088896341f), 0.5f));
    float tmp = __fmul_rn(0.693359375f, fx);
    float z   = __fmul_rn(-2.12194440e-4f, fx);
    float r   = __fsub_rn(__fsub_rn(x, tmp), z);
    z = __fmul_rn(r, r);
    float y = __fadd_rn(__fmul_rn(r, 1.9875691500E-4f), 1.3981999507E-3f);
    y = __fadd_rn(__fmul_rn(y, r), 8.3334519073E-3f);
    y = __fadd_rn(__fmul_rn(y, r), 4.1665795894E-2f);
    y = __fadd_rn(__fmul_rn(y, r), 1.6666665459E-1f);
    y = __fadd_rn(__fmul_rn(y, r), 5.0000001201E-1f);
    y = __fadd_rn(__fmul_rn(y, z), r);
    y = __fadd_rn(1.0f, y);
    int emm0 = ((int)fx + 0x7f) << 23;
    float p2n = __int_as_float(emm0);
    return fmaxf(__fmul_rn(y, p2n), v);
}

__device__ __forceinline__ float xla_sigmoid(float x) {
    return __fdiv_rn(1.0f, __fadd_rn(1.0f, xla_cpu_expf(-x)));
}

// ---------------- stage 1: per-anchor decode (4 anchors / thread) ----------
// Monotone-sigmoid fast path (top-2 logit gap > 1e-3 and m1 <= 8) -> 2 exps;
// else exact 80-sigmoid first-wins scan. float4 loads: every level size and
// offset is 4-divisible, so groups never straddle levels/rows.
__global__ void k_decode(InPtrs p) {
    int v = blockIdx.x * blockDim.x + threadIdx.x;
    int b = blockIdx.y;
    if (v >= NA / 4) return;
    int a0 = v * 4;

    int l, base;
    if      (a0 < 16384) { l = 0; base = 0; }
    else if (a0 < 20480) { l = 1; base = 16384; }
    else if (a0 < 21504) { l = 2; base = 20480; }
    else if (a0 < 21760) { l = 3; base = 21504; }
    else                 { l = 4; base = 21760; }

    int local = a0 - base;
    int lw = 7 - l, hw = 1 << (2 * lw), s = 8 << l;
    int yy = local >> lw, xx = local & ((1 << lw) - 1);
    float cy  = (float)(yy * s + (s >> 1));
    float cx0 = (float)(xx * s + (s >> 1));
    float fs  = (float)s;

    const float*  cb  = p.cls[l] + (size_t)b * 80 * hw + local;
    const float4* cb4 = (const float4*)cb;
    int hw4 = hw >> 2;

    float m1[4], m2[4];
    int   i1[4];
    {
        float4 f = cb4[0];
        m1[0]=f.x; m1[1]=f.y; m1[2]=f.z; m1[3]=f.w;
#pragma unroll
        for (int k = 0; k < 4; k++) { m2[k] = -1e30f; i1[k] = 0; }
    }
#pragma unroll 4
    for (int c = 1; c < 80; c++) {
        float4 f = cb4[(size_t)c * hw4];
        float vv[4] = {f.x, f.y, f.z, f.w};
#pragma unroll
        for (int k = 0; k < 4; k++) {
            bool gt = vv[k] > m1[k];
            m2[k] = gt ? m1[k] : fmaxf(m2[k], vv[k]);
            i1[k] = gt ? c : i1[k];
            m1[k] = gt ? vv[k] : m1[k];
        }
    }

    float4 cn4 = *(const float4*)(p.cnt[l] + (size_t)b * hw + local);
    float cnt[4] = {cn4.x, cn4.y, cn4.z, cn4.w};

    const float* rb = p.reg[l] + (size_t)b * 4 * hw + local;
    float4 r0v = *(const float4*)(rb);
    float4 r1v = *(const float4*)(rb + (size_t)hw);
    float4 r2v = *(const float4*)(rb + (size_t)2 * hw);
    float4 r3v = *(const float4*)(rb + (size_t)3 * hw);
    float r0[4] = {r0v.x, r0v.y, r0v.z, r0v.w};
    float r1[4] = {r1v.x, r1v.y, r1v.z, r1v.w};
    float r2[4] = {r2v.x, r2v.y, r2v.z, r2v.w};
    float r3[4] = {r3v.x, r3v.y, r3v.z, r3v.w};

    float sc[4]; int cl[4];
#pragma unroll
    for (int k = 0; k < 4; k++) {
        float best; int bi;
        if (m1[k] <= 8.0f && m2[k] < __fadd_rn(m1[k], -1e-3f)) {
            best = xla_sigmoid(m1[k]);
            bi   = i1[k];
        } else {
            // exact reference semantics: first-wins argmax over sigmoids
            best = xla_sigmoid(cb[k]); bi = 0;
            for (int c = 1; c < 80; c++) {
                float t = xla_sigmoid(cb[(size_t)c * hw + k]);
                if (t > best) { best = t; bi = c; }
            }
        }
        sc[k] = __fsqrt_rn(__fmul_rn(best, xla_sigmoid(cnt[k])));
        cl[k] = bi + 1;
    }

    size_t o  = (size_t)b * NA + a0;
    ((float4*)g_score)[o >> 2] = make_float4(sc[0], sc[1], sc[2], sc[3]);
    ((int4*)g_cls)[o >> 2]     = make_int4(cl[0], cl[1], cl[2], cl[3]);
#pragma unroll
    for (int k = 0; k < 4; k++) {
        float cx = __fadd_rn(cx0, (float)k * fs);
        g_box[o + k] = make_float4(__fsub_rn(cx, r0[k]), __fsub_rn(cy, r1[k]),
                                   __fadd_rn(cx, r2[k]), __fadd_rn(cy, r3[k]));
    }
}

// ---------------- stage 2: exact top-1000 + gather (fused, per batch) ------
__global__ void k_topk_gather() {
    int b = blockIdx.x;
    int t = threadIdx.x;

    __shared__ unsigned hist[NBINS];               // 32KB
    __shared__ unsigned long long s_keys[SORTN];   // 16KB
    __shared__ unsigned s_part[1024];
    __shared__ int sT, sT2, sCntGt;
    __shared__ int s_nsel;

    const float* sp = g_score + (size_t)b * NA;

    // ---- pass 1: coarse histogram on bits>>17 ----
    for (int i = t; i < NBINS; i += 1024) hist[i] = 0;
    __syncthreads();
    for (int a = t; a < NA; a += 1024) {
        unsigned bits = __float_as_uint(sp[a]);    // scores in (0,1)
        atomicAdd(&hist[bits >> 17], 1u);
    }
    __syncthreads();

    {   // suffix scan over 8 bins/thread chunks
        int base = t * 8;
        unsigned loc[8], csum = 0;
#pragma unroll
        for (int q = 0; q < 8; q++) { loc[q] = hist[base + q]; csum += loc[q]; }
        s_part[t] = csum;
        __syncthreads();
        for (int o = 1; o < 1024; o <<= 1) {
            unsigned add = (t + o < 1024) ? s_part[t + o] : 0u;
            __syncthreads();
            s_part[t] += add;
            __syncthreads();
        }
        unsigned inc = s_part[t];
        unsigned exc = inc - csum;
        if (exc < KTOP && inc >= KTOP) {
            unsigned run = exc;
            for (int q = 7; q >= 0; q--) {
                unsigned nxt = run + loc[q];
                if (nxt >= KTOP) { sT = base + q; sCntGt = (int)run; break; }
                run = nxt;
            }
        }
    }
    __syncthreads();
    unsigned T = (unsigned)sT;
    int k2 = KTOP - sCntGt;

    // ---- pass 2: refine inside bin T with bits[4..16] ----
    for (int i = t; i < NBINS; i += 1024) hist[i] = 0;
    __syncthreads();
    for (int a = t; a < NA; a += 1024) {
        unsigned bits = __float_as_uint(sp[a]);
        if ((bits >> 17) == T)
            atomicAdd(&hist[(bits >> 4) & 0x1FFFu], 1u);
    }
    __syncthreads();
    {
        int base = t * 8;
        unsigned loc[8], csum = 0;
#pragma unroll
        for (int q = 0; q < 8; q++) { loc[q] = hist[base + q]; csum += loc[q]; }
        s_part[t] = csum;
        __syncthreads();
        for (int o = 1; o < 1024; o <<= 1) {
            unsigned add = (t + o < 1024) ? s_part[t + o] : 0u;
            __syncthreads();
            s_part[t] += add;
            __syncthreads();
        }
        unsigned inc = s_part[t];
        unsigned exc = inc - csum;
        if ((int)exc < k2 && (int)inc >= k2) {
            unsigned run = exc;
            for (int q = 7; q >= 0; q--) {
                run += loc[q];
                if ((int)run >= k2) { sT2 = base + q; break; }
            }
        }
        if (t == 0) s_nsel = 0;
    }
    __syncthreads();
    unsigned T2 = (unsigned)sT2;

    // ---- compact candidates, sort 2048 ----
    for (int i = t; i < SORTN; i += 1024) s_keys[i] = 0ULL;
    __syncthreads();
    for (int a = t; a < NA; a += 1024) {
        unsigned bits = __float_as_uint(sp[a]);
        unsigned hb = bits >> 17;
        bool cand = (hb > T) || (hb == T && ((bits >> 4) & 0x1FFFu) >= T2);
        if (cand) {
            int pos = atomicAdd(&s_nsel, 1);
            if (pos < SORTN)
                s_keys[pos] = ((unsigned long long)bits << 32) |
                              (unsigned)(0xFFFFFFFFu - (unsigned)a);
        }
    }
    __syncthreads();

    for (int k = 2; k <= SORTN; k <<= 1) {
        for (int j = k >> 1; j > 0; j >>= 1) {
            for (int e = t; e < SORTN; e += 1024) {
                int pr = e ^ j;
                if (pr > e) {
                    unsigned long long A = s_keys[e], Bv = s_keys[pr];
                    bool up = ((e & k) == 0);
                    if ((A > Bv) == up) { s_keys[e] = Bv; s_keys[pr] = A; }
                }
            }
            __syncthreads();
        }
    }

    // ---- gather payload + maxc + offset boxes (fused) ----
    float  m = -1e30f;
    float4 box = make_float4(0.f, 0.f, 0.f, 0.f);
    int    cls = 0;
    if (t < KTOP) {
        unsigned long long key = s_keys[SORTN - 1 - t];
        unsigned bits = (unsigned)(key >> 32);
        int a = (int)(0xFFFFFFFFu - (unsigned)key);
        g_top_idx[b * KTOP + t]   = a;
        g_top_score[b * KTOP + t] = __uint_as_float(bits);
        box = g_box[(size_t)b * NA + a];
        cls = g_cls[(size_t)b * NA + a];
        g_top_box[b * KTOP + t] = box;
        g_top_cls[b * KTOP + t] = cls;
        m = fmaxf(fmaxf(box.x, box.y), fmaxf(box.z, box.w));
    }
    __syncthreads();
    float* s_red = (float*)s_part;
    s_red[t] = m;
    __syncthreads();
    for (int o = 512; o > 0; o >>= 1) {
        if (t < o) s_red[t] = fmaxf(s_red[t], s_red[t + o]);
        __syncthreads();
    }
    float maxc = s_red[0];

    if (t < KTOP) {
        float off = __fmul_rn((float)cls, __fadd_rn(maxc, 1.0f));
        float x1 = __fadd_rn(box.x, off), y1 = __fadd_rn(box.y, off);
        float x2 = __fadd_rn(box.z, off), y2 = __fadd_rn(box.w, off);
        g_nx[b * KTOP + t]   = make_float4(x1, y1, x2, y2);
        g_area[b * KTOP + t] = __fmul_rn(__fadd_rn(__fsub_rn(x2, x1), 1.0f),
                                         __fadd_rn(__fsub_rn(y2, y1), 1.0f));
    }
}

// ---------------- stage 3: suppression bitmask — upper triangle only -------
// NMS only consults suppression from earlier (higher-scored) rows, i.e. bits
// j > i of row i's mask. Block gx computes words g in [gx, 31] only; the
// lower-triangle words are left unwritten and their (garbage) contents are
// provably never consumed by k_nms_out (removed-bits for already-resolved
// words are never re-read).
__global__ void k_mask() {
    int b    = blockIdx.y;
    int gx   = blockIdx.x;
    int tid  = threadIdx.x;
    int warp = tid >> 5;
    int lane = tid & 31;

    __shared__ float sx1[KTOP], sy1[KTOP], sx2[KTOP], sy2[KTOP], sa[KTOP];
    for (int i = tid; i < KTOP; i += 1024) {
        float4 v = g_nx[b * KTOP + i];
        sx1[i] = v.x; sy1[i] = v.y; sx2[i] = v.z; sy2[i] = v.w;
        sa[i]  = g_area[b * KTOP + i];
    }
    __syncthreads();

    int i = gx * 32 + warp;
    if (i >= KTOP) return;

    float x1 = sx1[i], y1 = sy1[i], x2 = sx2[i], y2 = sy2[i], ar = sa[i];
    unsigned myword = 0;
    for (int g = gx; g < 32; g++) {
        int j = g * 32 + lane;
        bool sup = false;
        if (j < KTOP) {
            float xx1 = fmaxf(x1, sx1[j]);
            float yy1 = fmaxf(y1, sy1[j]);
            float xx2 = fminf(x2, sx2[j]);
            float yy2 = fminf(y2, sy2[j]);
            float inter = __fmul_rn(fmaxf(__fsub_rn(xx2, xx1), 0.0f),
                                    fmaxf(__fsub_rn(yy2, yy1), 0.0f));
            float denom = __fsub_rn(__fadd_rn(ar, sa[j]), inter);
            sup = __fdiv_rn(inter, denom) > IOU_THR;
        }
        unsigned bal = __ballot_sync(0xffffffffu, sup);
        if (lane == g) myword = bal;
    }
    if (lane >= gx)
        g_mask[((size_t)b * KTOP + i) * 32 + lane] = myword;
}

// ---------------- stage 4+5: word-serial NMS + output (prefetched) ---------
__global__ void k_nms_out(float* out) {
    int b   = blockIdx.x;
    int tid = threadIdx.x;
    __shared__ unsigned s_keep[32];

    if (tid < 32) {
        int lane = tid;
        unsigned validw = 0;
        for (int w = 0; w < 32; w++) {
            int row = w * 32 + lane;
            bool vv = (row < KTOP) && (g_top_score[b * KTOP + row] >= SCORE_THR);
            unsigned bal = __ballot_sync(0xffffffffu, vv);
            if (lane == w) validw = bal;
        }

        const unsigned* mp = g_mask + (size_t)b * KTOP * 32;
        unsigned mrow[32], mnext[32];
#pragma unroll
        for (int q = 0; q < 32; q++)
            mrow[q] = (q < KTOP) ? mp[(size_t)q * 32 + lane] : 0u;

        unsigned removed = 0, keepmine = 0;
        for (int w = 0; w < 32; w++) {
            if (w < 31) {          // prefetch next 32x32 word-block
#pragma unroll
                for (int q = 0; q < 32; q++) {
                    int row = (w + 1) * 32 + q;
                    mnext[q] = (row < KTOP) ? mp[(size_t)row * 32 + lane] : 0u;
                }
            }
            unsigned kw = 0;
            if (lane == w) {       // serial resolve of own word (diagonal)
#pragma unroll
                for (int q = 0; q < 32; q++) {
                    int row = w * 32 + q;
                    if (row < KTOP) {
                        bool ok = ((validw >> q) & 1u) && !((removed >> q) & 1u);
                        if (ok) { kw |= 1u << q; removed |= mrow[q]; }
                    }
                }
            }
            kw = __shfl_sync(0xffffffffu, kw, w);
            if (lane == w) keepmine = kw;
#pragma unroll
            for (int q = 0; q < 32; q++)
                if ((kw >> q) & 1u) removed |= mrow[q];
#pragma unroll
            for (int q = 0; q < 32; q++) mrow[q] = mnext[q];
        }
        s_keep[lane] = keepmine;
    }
    __syncthreads();

    for (int i = tid; i < KTOP; i += blockDim.x) {
        int g = b * KTOP + i;
        int keep = (s_keep[i >> 5] >> (i & 31)) & 1;

        float  s  = g_top_score[g];
        int    c  = g_top_cls[g];
        float4 bx = g_top_box[g];
        float x1 = fminf(fmaxf(bx.x, 0.0f), 1023.0f);
        float y1 = fminf(fmaxf(bx.y, 0.0f), 1023.0f);
        float x2 = fminf(fmaxf(bx.z, 0.0f), 1023.0f);
        float y2 = fminf(fmaxf(bx.w, 0.0f), 1023.0f);

        out[g]                = keep ? s : 0.0f;
        out[BATCH * KTOP + g] = keep ? (float)c : 0.0f;
        float* bo = out + 2 * BATCH * KTOP + (size_t)g * 4;
        bo[0] = keep ? x1 : 0.0f;
        bo[1] = keep ? y1 : 0.0f;
        bo[2] = keep ? x2 : 0.0f;
        bo[3] = keep ? y2 : 0.0f;
    }
}

// ---------------- launch ----------------------------------------------------
extern "C" void kernel_launch(void* const* d_in, const int* in_sizes, int n_in,
                              void* d_out, int out_size) {
    InPtrs P;
    for (int l = 0; l < 5; l++) { P.cls[l] = nullptr; P.cnt[l] = nullptr; P.reg[l] = nullptr; }
    bool seen131072 = false, seen32768 = false, seen8192 = false, seen2048 = false;

    for (int i = 0; i < n_in; i++) {
        const float* p = (const float*)d_in[i];
        switch (in_sizes[i]) {
            case 10485760: P.cls[0] = p; break;
            case 2621440:  P.cls[1] = p; break;
            case 655360:   P.cls[2] = p; break;
            case 163840:   P.cls[3] = p; break;
            case 40960:    P.cls[4] = p; break;
            case 524288:   P.reg[0] = p; break;
            case 512:      P.cnt[4] = p; break;
            case 131072:   if (!seen131072) { P.cnt[0] = p; seen131072 = true; } else P.reg[1] = p; break;
            case 32768:    if (!seen32768)  { P.cnt[1] = p; seen32768 = true; }  else P.reg[2] = p; break;
            case 8192:     if (!seen8192)   { P.cnt[2] = p; seen8192 = true; }   else P.reg[3] = p; break;
            case 2048:     if (!seen2048)   { P.cnt[3] = p; seen2048 = true; }   else P.reg[4] = p; break;
            default: break; // batch_imgs unused (shape only)
        }
    }

    dim3 gdec((NA / 4 + 255) / 256, BATCH);
    k_decode<<<gdec, 256>>>(P);
    k_topk_gather<<<BATCH, 1024>>>();
    k_mask<<<dim3(32, BATCH), 1024>>>();
    k_nms_out<<<BATCH, 256>>>((float*)d_out);
    (void)out_size;
}

// round 10
// speedup vs baseline: 1.0022x; 1.0022x over previous
#include <cuda_runtime.h>
#include <math.h>

#define NA    21824      // total anchors per image
#define BATCH 8
#define NBINS 8192
#define KTOP  1000
#define SORTN 2048
#define IOU_THR 0.6f
#define SCORE_THR 0.05f

struct InPtrs {
    const float* cls[5];
    const float* cnt[5];
    const float* reg[5];
};

// ---------------- scratch (device globals; no allocation allowed) ----------
__device__ float    g_score[BATCH * NA];
__device__ int      g_cls  [BATCH * NA];
__device__ float4   g_box  [BATCH * NA];

__device__ int      g_top_idx  [BATCH * KTOP];
__device__ float    g_top_score[BATCH * KTOP];
__device__ int      g_top_cls  [BATCH * KTOP];
__device__ float4   g_top_box  [BATCH * KTOP];

__device__ float4   g_nx   [BATCH * KTOP];   // class-offset boxes
__device__ float    g_area [BATCH * KTOP];

__device__ __align__(16) unsigned g_mask [BATCH * KTOP * 32]; // suppression bitmask

// Bit-exact replica of XLA:CPU's GenerateVF32Exp (Cephes expf, unfused
// mul/add). Verified bit-exact against the reference in R6.
__device__ __forceinline__ float xla_cpu_expf(float v) {
    float x = fminf(fmaxf(v, -88.3762626647949f), 88.3762626647950f);
    float fx = floorf(__fadd_rn(__fmul_rn(x, 1.44269504088896341f), 0.5f));
    float tmp = __fmul_rn(0.693359375f, fx);
    float z   = __fmul_rn(-2.12194440e-4f, fx);
    float r   = __fsub_rn(__fsub_rn(x, tmp), z);
    z = __fmul_rn(r, r);
    float y = __fadd_rn(__fmul_rn(r, 1.9875691500E-4f), 1.3981999507E-3f);
    y = __fadd_rn(__fmul_rn(y, r), 8.3334519073E-3f);
    y = __fadd_rn(__fmul_rn(y, r), 4.1665795894E-2f);
    y = __fadd_rn(__fmul_rn(y, r), 1.6666665459E-1f);
    y = __fadd_rn(__fmul_rn(y, r), 5.0000001201E-1f);
    y = __fadd_rn(__fmul_rn(y, z), r);
    y = __fadd_rn(1.0f, y);
    int emm0 = ((int)fx + 0x7f) << 23;
    float p2n = __int_as_float(emm0);
    return fmaxf(__fmul_rn(y, p2n), v);
}

__device__ __forceinline__ float xla_sigmoid(float x) {
    return __fdiv_rn(1.0f, __fadd_rn(1.0f, xla_cpu_expf(-x)));
}

// ---------------- stage 1: per-anchor decode (4 anchors / thread) ----------
__global__ void k_decode(InPtrs p) {
    int v = blockIdx.x * blockDim.x + threadIdx.x;
    int b = blockIdx.y;
    if (v >= NA / 4) return;
    int a0 = v * 4;

    int l, base;
    if      (a0 < 16384) { l = 0; base = 0; }
    else if (a0 < 20480) { l = 1; base = 16384; }
    else if (a0 < 21504) { l = 2; base = 20480; }
    else if (a0 < 21760) { l = 3; base = 21504; }
    else                 { l = 4; base = 21760; }

    int local = a0 - base;
    int lw = 7 - l, hw = 1 << (2 * lw), s = 8 << l;
    int yy = local >> lw, xx = local & ((1 << lw) - 1);
    float cy  = (float)(yy * s + (s >> 1));
    float cx0 = (float)(xx * s + (s >> 1));
    float fs  = (float)s;

    const float*  cb  = p.cls[l] + (size_t)b * 80 * hw + local;
    const float4* cb4 = (const float4*)cb;
    int hw4 = hw >> 2;

    float m1[4], m2[4];
    int   i1[4];
    {
        float4 f = cb4[0];
        m1[0]=f.x; m1[1]=f.y; m1[2]=f.z; m1[3]=f.w;
#pragma unroll
        for (int k = 0; k < 4; k++) { m2[k] = -1e30f; i1[k] = 0; }
    }
#pragma unroll 4
    for (int c = 1; c < 80; c++) {
        float4 f = cb4[(size_t)c * hw4];
        float vv[4] = {f.x, f.y, f.z, f.w};
#pragma unroll
        for (int k = 0; k < 4; k++) {
            bool gt = vv[k] > m1[k];
            m2[k] = gt ? m1[k] : fmaxf(m2[k], vv[k]);
            i1[k] = gt ? c : i1[k];
            m1[k] = gt ? vv[k] : m1[k];
        }
    }

    float4 cn4 = *(const float4*)(p.cnt[l] + (size_t)b * hw + local);
    float cnt[4] = {cn4.x, cn4.y, cn4.z, cn4.w};

    const float* rb = p.reg[l] + (size_t)b * 4 * hw + local;
    float4 r0v = *(const float4*)(rb);
    float4 r1v = *(const float4*)(rb + (size_t)hw);
    float4 r2v = *(const float4*)(rb + (size_t)2 * hw);
    float4 r3v = *(const float4*)(rb + (size_t)3 * hw);
    float r0[4] = {r0v.x, r0v.y, r0v.z, r0v.w};
    float r1[4] = {r1v.x, r1v.y, r1v.z, r1v.w};
    float r2[4] = {r2v.x, r2v.y, r2v.z, r2v.w};
    float r3[4] = {r3v.x, r3v.y, r3v.z, r3v.w};

    float sc[4]; int cl[4];
#pragma unroll
    for (int k = 0; k < 4; k++) {
        float best; int bi;
        if (m1[k] <= 8.0f && m2[k] < __fadd_rn(m1[k], -1e-3f)) {
            best = xla_sigmoid(m1[k]);
            bi   = i1[k];
        } else {
            // exact reference semantics: first-wins argmax over sigmoids
            best = xla_sigmoid(cb[k]); bi = 0;
            for (int c = 1; c < 80; c++) {
                float t = xla_sigmoid(cb[(size_t)c * hw + k]);
                if (t > best) { best = t; bi = c; }
            }
        }
        sc[k] = __fsqrt_rn(__fmul_rn(best, xla_sigmoid(cnt[k])));
        cl[k] = bi + 1;
    }

    size_t o  = (size_t)b * NA + a0;
    ((float4*)g_score)[o >> 2] = make_float4(sc[0], sc[1], sc[2], sc[3]);
    ((int4*)g_cls)[o >> 2]     = make_int4(cl[0], cl[1], cl[2], cl[3]);
#pragma unroll
    for (int k = 0; k < 4; k++) {
        float cx = __fadd_rn(cx0, (float)k * fs);
        g_box[o + k] = make_float4(__fsub_rn(cx, r0[k]), __fsub_rn(cy, r1[k]),
                                   __fadd_rn(cx, r2[k]), __fadd_rn(cy, r3[k]));
    }
}

// ---------------- stage 2: exact top-1000 + gather (fused, per batch) ------
__global__ void k_topk_gather() {
    int b = blockIdx.x;
    int t = threadIdx.x;

    __shared__ unsigned hist[NBINS];               // 32KB
    __shared__ unsigned long long s_keys[SORTN];   // 16KB
    __shared__ unsigned s_part[1024];
    __shared__ int sT, sT2, sCntGt;
    __shared__ int s_nsel;

    const float* sp = g_score + (size_t)b * NA;

    for (int i = t; i < NBINS; i += 1024) hist[i] = 0;
    __syncthreads();
    for (int a = t; a < NA; a += 1024) {
        unsigned bits = __float_as_uint(sp[a]);
        atomicAdd(&hist[bits >> 17], 1u);
    }
    __syncthreads();

    {
        int base = t * 8;
        unsigned loc[8], csum = 0;
#pragma unroll
        for (int q = 0; q < 8; q++) { loc[q] = hist[base + q]; csum += loc[q]; }
        s_part[t] = csum;
        __syncthreads();
        for (int o = 1; o < 1024; o <<= 1) {
            unsigned add = (t + o < 1024) ? s_part[t + o] : 0u;
            __syncthreads();
            s_part[t] += add;
            __syncthreads();
        }
        unsigned inc = s_part[t];
        unsigned exc = inc - csum;
        if (exc < KTOP && inc >= KTOP) {
            unsigned run = exc;
            for (int q = 7; q >= 0; q--) {
                unsigned nxt = run + loc[q];
                if (nxt >= KTOP) { sT = base + q; sCntGt = (int)run; break; }
                run = nxt;
            }
        }
    }
    __syncthreads();
    unsigned T = (unsigned)sT;
    int k2 = KTOP - sCntGt;

    for (int i = t; i < NBINS; i += 1024) hist[i] = 0;
    __syncthreads();
    for (int a = t; a < NA; a += 1024) {
        unsigned bits = __float_as_uint(sp[a]);
        if ((bits >> 17) == T)
            atomicAdd(&hist[(bits >> 4) & 0x1FFFu], 1u);
    }
    __syncthreads();
    {
        int base = t * 8;
        unsigned loc[8], csum = 0;
#pragma unroll
        for (int q = 0; q < 8; q++) { loc[q] = hist[base + q]; csum += loc[q]; }
        s_part[t] = csum;
        __syncthreads();
        for (int o = 1; o < 1024; o <<= 1) {
            unsigned add = (t + o < 1024) ? s_part[t + o] : 0u;
            __syncthreads();
            s_part[t] += add;
            __syncthreads();
        }
        unsigned inc = s_part[t];
        unsigned exc = inc - csum;
        if ((int)exc < k2 && (int)inc >= k2) {
            unsigned run = exc;
            for (int q = 7; q >= 0; q--) {
                run += loc[q];
                if ((int)run >= k2) { sT2 = base + q; break; }
            }
        }
        if (t == 0) s_nsel = 0;
    }
    __syncthreads();
    unsigned T2 = (unsigned)sT2;

    for (int i = t; i < SORTN; i += 1024) s_keys[i] = 0ULL;
    __syncthreads();
    for (int a = t; a < NA; a += 1024) {
        unsigned bits = __float_as_uint(sp[a]);
        unsigned hb = bits >> 17;
        bool cand = (hb > T) || (hb == T && ((bits >> 4) & 0x1FFFu) >= T2);
        if (cand) {
            int pos = atomicAdd(&s_nsel, 1);
            if (pos < SORTN)
                s_keys[pos] = ((unsigned long long)bits << 32) |
                              (unsigned)(0xFFFFFFFFu - (unsigned)a);
        }
    }
    __syncthreads();

    for (int k = 2; k <= SORTN; k <<= 1) {
        for (int j = k >> 1; j > 0; j >>= 1) {
            for (int e = t; e < SORTN; e += 1024) {
                int pr = e ^ j;
                if (pr > e) {
                    unsigned long long A = s_keys[e], Bv = s_keys[pr];
                    bool up = ((e & k) == 0);
                    if ((A > Bv) == up) { s_keys[e] = Bv; s_keys[pr] = A; }
                }
            }
            __syncthreads();
        }
    }

    // ---- gather payload + maxc + offset boxes (fused) ----
    float  m = -1e30f;
    float4 box = make_float4(0.f, 0.f, 0.f, 0.f);
    int    cls = 0;
    if (t < KTOP) {
        unsigned long long key = s_keys[SORTN - 1 - t];
        unsigned bits = (unsigned)(key >> 32);
        int a = (int)(0xFFFFFFFFu - (unsigned)key);
        g_top_idx[b * KTOP + t]   = a;
        g_top_score[b * KTOP + t] = __uint_as_float(bits);
        box = g_box[(size_t)b * NA + a];
        cls = g_cls[(size_t)b * NA + a];
        g_top_box[b * KTOP + t] = box;
        g_top_cls[b * KTOP + t] = cls;
        m = fmaxf(fmaxf(box.x, box.y), fmaxf(box.z, box.w));
    }
    __syncthreads();
    float* s_red = (float*)s_part;
    s_red[t] = m;
    __syncthreads();
    for (int o = 512; o > 0; o >>= 1) {
        if (t < o) s_red[t] = fmaxf(s_red[t], s_red[t + o]);
        __syncthreads();
    }
    float maxc = s_red[0];

    if (t < KTOP) {
        float off = __fmul_rn((float)cls, __fadd_rn(maxc, 1.0f));
        float x1 = __fadd_rn(box.x, off), y1 = __fadd_rn(box.y, off);
        float x2 = __fadd_rn(box.z, off), y2 = __fadd_rn(box.w, off);
        g_nx[b * KTOP + t]   = make_float4(x1, y1, x2, y2);
        g_area[b * KTOP + t] = __fmul_rn(__fadd_rn(__fsub_rn(x2, x1), 1.0f),
                                         __fadd_rn(__fsub_rn(y2, y1), 1.0f));
    }
}

// ---------------- stage 3: suppression bitmask — upper triangle only -------
__global__ void k_mask() {
    int b    = blockIdx.y;
    int gx   = blockIdx.x;
    int tid  = threadIdx.x;
    int warp = tid >> 5;
    int lane = tid & 31;

    __shared__ float sx1[KTOP], sy1[KTOP], sx2[KTOP], sy2[KTOP], sa[KTOP];
    for (int i = tid; i < KTOP; i += 1024) {
        float4 v = g_nx[b * KTOP + i];
        sx1[i] = v.x; sy1[i] = v.y; sx2[i] = v.z; sy2[i] = v.w;
        sa[i]  = g_area[b * KTOP + i];
    }
    __syncthreads();

    int i = gx * 32 + warp;
    if (i >= KTOP) return;

    float x1 = sx1[i], y1 = sy1[i], x2 = sx2[i], y2 = sy2[i], ar = sa[i];
    unsigned myword = 0;
    for (int g = gx; g < 32; g++) {
        int j = g * 32 + lane;
        bool sup = false;
        if (j < KTOP) {
            float xx1 = fmaxf(x1, sx1[j]);
            float yy1 = fmaxf(y1, sy1[j]);
            float xx2 = fminf(x2, sx2[j]);
            float yy2 = fminf(y2, sy2[j]);
            float inter = __fmul_rn(fmaxf(__fsub_rn(xx2, xx1), 0.0f),
                                    fmaxf(__fsub_rn(yy2, yy1), 0.0f));
            float denom = __fsub_rn(__fadd_rn(ar, sa[j]), inter);
            sup = __fdiv_rn(inter, denom) > IOU_THR;
        }
        unsigned bal = __ballot_sync(0xffffffffu, sup);
        if (lane == g) myword = bal;
    }
    if (lane >= gx)
        g_mask[((size_t)b * KTOP + i) * 32 + lane] = myword;
}

// ---------------- stage 4+5: NMS from SHARED-staged mask + output ----------
// Phase 1: all 1024 threads stage the 125KB mask block into dynamic shared
// (one overlapped burst; kills the per-iteration 600-cyc L2/DRAM round trips
// that made R8's version latency-bound at occ=12%). Phase 2: warp 0 runs the
// serial greedy resolve against LDS. Phase 3: all threads write outputs.
__global__ void k_nms_out(float* out) {
    extern __shared__ unsigned smask[];        // KTOP*32 = 32000 words
    __shared__ unsigned s_keep[32];

    int b   = blockIdx.x;
    int tid = threadIdx.x;

    const unsigned* mp = g_mask + (size_t)b * KTOP * 32;
    const uint4* mp4 = (const uint4*)mp;
    uint4* sm4 = (uint4*)smask;
    for (int i = tid; i < KTOP * 32 / 4; i += 1024) sm4[i] = mp4[i];
    __syncthreads();

    if (tid < 32) {
        int lane = tid;
        // batched score loads (32 independent, full MLP), THEN ballots
        float vsc[32];
#pragma unroll
        for (int w = 0; w < 32; w++) {
            int row = w * 32 + lane;
            vsc[w] = (row < KTOP) ? g_top_score[b * KTOP + row] : -1.0f;
        }
        unsigned validw = 0;
#pragma unroll
        for (int w = 0; w < 32; w++) {
            unsigned bal = __ballot_sync(0xffffffffu, vsc[w] >= SCORE_THR);
            if (lane == w) validw = bal;
        }

        unsigned removed = 0, keepmine = 0;
        for (int w = 0; w < 32; w++) {
            unsigned mrow[32];
#pragma unroll
            for (int q = 0; q < 32; q++) {
                int row = w * 32 + q;
                mrow[q] = (row < KTOP) ? smask[row * 32 + lane] : 0u;
            }
            unsigned kw = 0;
            if (lane == w) {       // serial resolve of own word (diagonal)
#pragma unroll
                for (int q = 0; q < 32; q++) {
                    int row = w * 32 + q;
                    if (row < KTOP) {
                        bool ok = ((validw >> q) & 1u) && !((removed >> q) & 1u);
                        if (ok) { kw |= 1u << q; removed |= mrow[q]; }
                    }
                }
            }
            kw = __shfl_sync(0xffffffffu, kw, w);
            if (lane == w) keepmine = kw;
#pragma unroll
            for (int q = 0; q < 32; q++)
                if ((kw >> q) & 1u) removed |= mrow[q];
        }
        s_keep[lane] = keepmine;
    }
    __syncthreads();

    for (int i = tid; i < KTOP; i += blockDim.x) {
        int g = b * KTOP + i;
        int keep = (s_keep[i >> 5] >> (i & 31)) & 1;

        float  s  = g_top_score[g];
        int    c  = g_top_cls[g];
        float4 bx = g_top_box[g];
        float x1 = fminf(fmaxf(bx.x, 0.0f), 1023.0f);
        float y1 = fminf(fmaxf(bx.y, 0.0f), 1023.0f);
        float x2 = fminf(fmaxf(bx.z, 0.0f), 1023.0f);
        float y2 = fminf(fmaxf(bx.w, 0.0f), 1023.0f);

        out[g]                = keep ? s : 0.0f;
        out[BATCH * KTOP + g] = keep ? (float)c : 0.0f;
        float* bo = out + 2 * BATCH * KTOP + (size_t)g * 4;
        bo[0] = keep ? x1 : 0.0f;
        bo[1] = keep ? y1 : 0.0f;
        bo[2] = keep ? x2 : 0.0f;
        bo[3] = keep ? y2 : 0.0f;
    }
}

// ---------------- launch ----------------------------------------------------
extern "C" void kernel_launch(void* const* d_in, const int* in_sizes, int n_in,
                              void* d_out, int out_size) {
    InPtrs P;
    for (int l = 0; l < 5; l++) { P.cls[l] = nullptr; P.cnt[l] = nullptr; P.reg[l] = nullptr; }
    bool seen131072 = false, seen32768 = false, seen8192 = false, seen2048 = false;

    for (int i = 0; i < n_in; i++) {
        const float* p = (const float*)d_in[i];
        switch (in_sizes[i]) {
            case 10485760: P.cls[0] = p; break;
            case 2621440:  P.cls[1] = p; break;
            case 655360:   P.cls[2] = p; break;
            case 163840:   P.cls[3] = p; break;
            case 40960:    P.cls[4] = p; break;
            case 524288:   P.reg[0] = p; break;
            case 512:      P.cnt[4] = p; break;
            case 131072:   if (!seen131072) { P.cnt[0] = p; seen131072 = true; } else P.reg[1] = p; break;
            case 32768:    if (!seen32768)  { P.cnt[1] = p; seen32768 = true; }  else P.reg[2] = p; break;
            case 8192:     if (!seen8192)   { P.cnt[2] = p; seen8192 = true; }   else P.reg[3] = p; break;
            case 2048:     if (!seen2048)   { P.cnt[3] = p; seen2048 = true; }   else P.reg[4] = p; break;
            default: break; // batch_imgs unused (shape only)
        }
    }

    static bool attr_set = false;
    if (!attr_set) {
        cudaFuncSetAttribute(k_nms_out, cudaFuncAttributeMaxDynamicSharedMemorySize,
                             KTOP * 32 * (int)sizeof(unsigned));
        attr_set = true;
    }

    dim3 gdec((NA / 4 + 255) / 256, BATCH);
    k_decode<<<gdec, 256>>>(P);
    k_topk_gather<<<BATCH, 1024>>>();
    k_mask<<<dim3(32, BATCH), 1024>>>();
    k_nms_out<<<BATCH, 1024, KTOP * 32 * sizeof(unsigned)>>>((float*)d_out);
    (void)out_size;
}

// round 13
// speedup vs baseline: 1.1394x; 1.1370x over previous
#include <cuda_runtime.h>
#include <math.h>

#define NA    21824      // total anchors per image
#define BATCH 8
#define NBINS 8192
#define KTOP  1000
#define SORTN 2048
#define IOU_THR 0.6f
#define SCORE_THR 0.05f

#define MROWS 1024            // mask rows staged (padded; rows >= KTOP zeroed)
#define MSTRIDE 33            // shared stride (conflict-free diagonal reads)

struct InPtrs {
    const float* cls[5];
    const float* cnt[5];
    const float* reg[5];
};

// ---------------- scratch (device globals; no allocation allowed) ----------
__device__ float    g_score[BATCH * NA];
__device__ int      g_cls  [BATCH * NA];
__device__ float4   g_box  [BATCH * NA];

__device__ int      g_top_idx  [BATCH * KTOP];
__device__ float    g_top_score[BATCH * KTOP];
__device__ int      g_top_cls  [BATCH * KTOP];
__device__ float4   g_top_box  [BATCH * KTOP];

__device__ float4   g_nx   [BATCH * KTOP];   // class-offset boxes
__device__ float    g_area [BATCH * KTOP];

__device__ __align__(16) unsigned g_mask [BATCH * KTOP * 32]; // suppression bitmask

// Bit-exact replica of XLA:CPU's GenerateVF32Exp (Cephes expf, unfused
// mul/add). Verified bit-exact against the reference in R6.
__device__ __forceinline__ float xla_cpu_expf(float v) {
    float x = fminf(fmaxf(v, -88.3762626647949f), 88.3762626647950f);
    float fx = floorf(__fadd_rn(__fmul_rn(x, 1.44269504088896341f), 0.5f));
    float tmp = __fmul_rn(0.693359375f, fx);
    float z   = __fmul_rn(-2.12194440e-4f, fx);
    float r   = __fsub_rn(__fsub_rn(x, tmp), z);
    z = __fmul_rn(r, r);
    float y = __fadd_rn(__fmul_rn(r, 1.9875691500E-4f), 1.3981999507E-3f);
    y = __fadd_rn(__fmul_rn(y, r), 8.3334519073E-3f);
    y = __fadd_rn(__fmul_rn(y, r), 4.1665795894E-2f);
    y = __fadd_rn(__fmul_rn(y, r), 1.6666665459E-1f);
    y = __fadd_rn(__fmul_rn(y, r), 5.0000001201E-1f);
    y = __fadd_rn(__fmul_rn(y, z), r);
    y = __fadd_rn(1.0f, y);
    int emm0 = ((int)fx + 0x7f) << 23;
    float p2n = __int_as_float(emm0);
    return fmaxf(__fmul_rn(y, p2n), v);
}

__device__ __forceinline__ float xla_sigmoid(float x) {
    return __fdiv_rn(1.0f, __fadd_rn(1.0f, xla_cpu_expf(-x)));
}

// ---------------- stage 1: per-anchor decode (4 anchors / thread) ----------
__global__ void k_decode(InPtrs p) {
    int v = blockIdx.x * blockDim.x + threadIdx.x;
    int b = blockIdx.y;
    if (v >= NA / 4) return;
    int a0 = v * 4;

    int l, base;
    if      (a0 < 16384) { l = 0; base = 0; }
    else if (a0 < 20480) { l = 1; base = 16384; }
    else if (a0 < 21504) { l = 2; base = 20480; }
    else if (a0 < 21760) { l = 3; base = 21504; }
    else                 { l = 4; base = 21760; }

    int local = a0 - base;
    int lw = 7 - l, hw = 1 << (2 * lw), s = 8 << l;
    int yy = local >> lw, xx = local & ((1 << lw) - 1);
    float cy  = (float)(yy * s + (s >> 1));
    float cx0 = (float)(xx * s + (s >> 1));
    float fs  = (float)s;

    const float*  cb  = p.cls[l] + (size_t)b * 80 * hw + local;
    const float4* cb4 = (const float4*)cb;
    int hw4 = hw >> 2;

    float m1[4], m2[4];
    int   i1[4];
    {
        float4 f = cb4[0];
        m1[0]=f.x; m1[1]=f.y; m1[2]=f.z; m1[3]=f.w;
#pragma unroll
        for (int k = 0; k < 4; k++) { m2[k] = -1e30f; i1[k] = 0; }
    }
#pragma unroll 4
    for (int c = 1; c < 80; c++) {
        float4 f = cb4[(size_t)c * hw4];
        float vv[4] = {f.x, f.y, f.z, f.w};
#pragma unroll
        for (int k = 0; k < 4; k++) {
            bool gt = vv[k] > m1[k];
            m2[k] = gt ? m1[k] : fmaxf(m2[k], vv[k]);
            i1[k] = gt ? c : i1[k];
            m1[k] = gt ? vv[k] : m1[k];
        }
    }

    float4 cn4 = *(const float4*)(p.cnt[l] + (size_t)b * hw + local);
    float cnt[4] = {cn4.x, cn4.y, cn4.z, cn4.w};

    const float* rb = p.reg[l] + (size_t)b * 4 * hw + local;
    float4 r0v = *(const float4*)(rb);
    float4 r1v = *(const float4*)(rb + (size_t)hw);
    float4 r2v = *(const float4*)(rb + (size_t)2 * hw);
    float4 r3v = *(const float4*)(rb + (size_t)3 * hw);
    float r0[4] = {r0v.x, r0v.y, r0v.z, r0v.w};
    float r1[4] = {r1v.x, r1v.y, r1v.z, r1v.w};
    float r2[4] = {r2v.x, r2v.y, r2v.z, r2v.w};
    float r3[4] = {r3v.x, r3v.y, r3v.z, r3v.w};

    float sc[4]; int cl[4];
#pragma unroll
    for (int k = 0; k < 4; k++) {
        float best; int bi;
        if (m1[k] <= 8.0f && m2[k] < __fadd_rn(m1[k], -1e-3f)) {
            best = xla_sigmoid(m1[k]);
            bi   = i1[k];
        } else {
            // exact reference semantics: first-wins argmax over sigmoids
            best = xla_sigmoid(cb[k]); bi = 0;
            for (int c = 1; c < 80; c++) {
                float t = xla_sigmoid(cb[(size_t)c * hw + k]);
                if (t > best) { best = t; bi = c; }
            }
        }
        sc[k] = __fsqrt_rn(__fmul_rn(best, xla_sigmoid(cnt[k])));
        cl[k] = bi + 1;
    }

    size_t o  = (size_t)b * NA + a0;
    ((float4*)g_score)[o >> 2] = make_float4(sc[0], sc[1], sc[2], sc[3]);
    ((int4*)g_cls)[o >> 2]     = make_int4(cl[0], cl[1], cl[2], cl[3]);
#pragma unroll
    for (int k = 0; k < 4; k++) {
        float cx = __fadd_rn(cx0, (float)k * fs);
        g_box[o + k] = make_float4(__fsub_rn(cx, r0[k]), __fsub_rn(cy, r1[k]),
                                   __fadd_rn(cx, r2[k]), __fadd_rn(cy, r3[k]));
    }
}

// ---------------- stage 2: exact top-1000 + gather (fused, per batch) ------
__global__ void k_topk_gather() {
    int b = blockIdx.x;
    int t = threadIdx.x;

    __shared__ unsigned hist[NBINS];               // 32KB
    __shared__ unsigned long long s_keys[SORTN];   // 16KB
    __shared__ unsigned s_part[1024];
    __shared__ int sT, sT2, sCntGt;
    __shared__ int s_nsel;

    const float* sp = g_score + (size_t)b * NA;

    for (int i = t; i < NBINS; i += 1024) hist[i] = 0;
    __syncthreads();
    for (int a = t; a < NA; a += 1024) {
        unsigned bits = __float_as_uint(sp[a]);
        atomicAdd(&hist[bits >> 17], 1u);
    }
    __syncthreads();

    {
        int base = t * 8;
        unsigned loc[8], csum = 0;
#pragma unroll
        for (int q = 0; q < 8; q++) { loc[q] = hist[base + q]; csum += loc[q]; }
        s_part[t] = csum;
        __syncthreads();
        for (int o = 1; o < 1024; o <<= 1) {
            unsigned add = (t + o < 1024) ? s_part[t + o] : 0u;
            __syncthreads();
            s_part[t] += add;
            __syncthreads();
        }
        unsigned inc = s_part[t];
        unsigned exc = inc - csum;
        if (exc < KTOP && inc >= KTOP) {
            unsigned run = exc;
            for (int q = 7; q >= 0; q--) {
                unsigned nxt = run + loc[q];
                if (nxt >= KTOP) { sT = base + q; sCntGt = (int)run; break; }
                run = nxt;
            }
        }
    }
    __syncthreads();
    unsigned T = (unsigned)sT;
    int k2 = KTOP - sCntGt;

    for (int i = t; i < NBINS; i += 1024) hist[i] = 0;
    __syncthreads();
    for (int a = t; a < NA; a += 1024) {
        unsigned bits = __float_as_uint(sp[a]);
        if ((bits >> 17) == T)
            atomicAdd(&hist[(bits >> 4) & 0x1FFFu], 1u);
    }
    __syncthreads();
    {
        int base = t * 8;
        unsigned loc[8], csum = 0;
#pragma unroll
        for (int q = 0; q < 8; q++) { loc[q] = hist[base + q]; csum += loc[q]; }
        s_part[t] = csum;
        __syncthreads();
        for (int o = 1; o < 1024; o <<= 1) {
            unsigned add = (t + o < 1024) ? s_part[t + o] : 0u;
            __syncthreads();
            s_part[t] += add;
            __syncthreads();
        }
        unsigned inc = s_part[t];
        unsigned exc = inc - csum;
        if ((int)exc < k2 && (int)inc >= k2) {
            unsigned run = exc;
            for (int q = 7; q >= 0; q--) {
                run += loc[q];
                if ((int)run >= k2) { sT2 = base + q; break; }
            }
        }
        if (t == 0) s_nsel = 0;
    }
    __syncthreads();
    unsigned T2 = (unsigned)sT2;

    for (int i = t; i < SORTN; i += 1024) s_keys[i] = 0ULL;
    __syncthreads();
    for (int a = t; a < NA; a += 1024) {
        unsigned bits = __float_as_uint(sp[a]);
        unsigned hb = bits >> 17;
        bool cand = (hb > T) || (hb == T && ((bits >> 4) & 0x1FFFu) >= T2);
        if (cand) {
            int pos = atomicAdd(&s_nsel, 1);
            if (pos < SORTN)
                s_keys[pos] = ((unsigned long long)bits << 32) |
                              (unsigned)(0xFFFFFFFFu - (unsigned)a);
        }
    }
    __syncthreads();

    for (int k = 2; k <= SORTN; k <<= 1) {
        for (int j = k >> 1; j > 0; j >>= 1) {
            for (int e = t; e < SORTN; e += 1024) {
                int pr = e ^ j;
                if (pr > e) {
                    unsigned long long A = s_keys[e], Bv = s_keys[pr];
                    bool up = ((e & k) == 0);
                    if ((A > Bv) == up) { s_keys[e] = Bv; s_keys[pr] = A; }
                }
            }
            __syncthreads();
        }
    }

    // ---- gather payload + maxc + offset boxes (fused) ----
    float  m = -1e30f;
    float4 box = make_float4(0.f, 0.f, 0.f, 0.f);
    int    cls = 0;
    if (t < KTOP) {
        unsigned long long key = s_keys[SORTN - 1 - t];
        unsigned bits = (unsigned)(key >> 32);
        int a = (int)(0xFFFFFFFFu - (unsigned)key);
        g_top_idx[b * KTOP + t]   = a;
        g_top_score[b * KTOP + t] = __uint_as_float(bits);
        box = g_box[(size_t)b * NA + a];
        cls = g_cls[(size_t)b * NA + a];
        g_top_box[b * KTOP + t] = box;
        g_top_cls[b * KTOP + t] = cls;
        m = fmaxf(fmaxf(box.x, box.y), fmaxf(box.z, box.w));
    }
    __syncthreads();
    float* s_red = (float*)s_part;
    s_red[t] = m;
    __syncthreads();
    for (int o = 512; o > 0; o >>= 1) {
        if (t < o) s_red[t] = fmaxf(s_red[t], s_red[t + o]);
        __syncthreads();
    }
    float maxc = s_red[0];

    if (t < KTOP) {
        float off = __fmul_rn((float)cls, __fadd_rn(maxc, 1.0f));
        float x1 = __fadd_rn(box.x, off), y1 = __fadd_rn(box.y, off);
        float x2 = __fadd_rn(box.z, off), y2 = __fadd_rn(box.w, off);
        g_nx[b * KTOP + t]   = make_float4(x1, y1, x2, y2);
        g_area[b * KTOP + t] = __fmul_rn(__fadd_rn(__fsub_rn(x2, x1), 1.0f),
                                         __fadd_rn(__fsub_rn(y2, y1), 1.0f));
    }
}

// ---------------- stage 3: suppression bitmask — upper triangle only -------
__global__ void k_mask() {
    int b    = blockIdx.y;
    int gx   = blockIdx.x;
    int tid  = threadIdx.x;
    int warp = tid >> 5;
    int lane = tid & 31;

    __shared__ float sx1[KTOP], sy1[KTOP], sx2[KTOP], sy2[KTOP], sa[KTOP];
    for (int i = tid; i < KTOP; i += 1024) {
        float4 v = g_nx[b * KTOP + i];
        sx1[i] = v.x; sy1[i] = v.y; sx2[i] = v.z; sy2[i] = v.w;
        sa[i]  = g_area[b * KTOP + i];
    }
    __syncthreads();

    int i = gx * 32 + warp;
    if (i >= KTOP) return;

    float x1 = sx1[i], y1 = sy1[i], x2 = sx2[i], y2 = sy2[i], ar = sa[i];
    unsigned myword = 0;
    for (int g = gx; g < 32; g++) {
        int j = g * 32 + lane;
        bool sup = false;
        if (j < KTOP) {
            float xx1 = fmaxf(x1, sx1[j]);
            float yy1 = fmaxf(y1, sy1[j]);
            float xx2 = fminf(x2, sx2[j]);
            float yy2 = fminf(y2, sy2[j]);
            float inter = __fmul_rn(fmaxf(__fsub_rn(xx2, xx1), 0.0f),
                                    fmaxf(__fsub_rn(yy2, yy1), 0.0f));
            float denom = __fsub_rn(__fadd_rn(ar, sa[j]), inter);
            sup = __fdiv_rn(inter, denom) > IOU_THR;
        }
        unsigned bal = __ballot_sync(0xffffffffu, sup);
        if (lane == g) myword = bal;
    }
    if (lane >= gx)
        g_mask[((size_t)b * KTOP + i) * 32 + lane] = myword;
}

// ---------------- stage 4+5: warp-parallel fixpoint NMS + output -----------
// Symmetric IoU => diagonal-block columns equal rows: lane q's suppression
// column within the 32x32 diagonal block is row (w*32+q)'s word w (one LDS,
// stride-33 => conflict-free). Greedy NMS within a word is the UNIQUE
// fixpoint of  K' = cand & ~ballot( K & below(q) & diag_q != 0 )
// (unique by induction on bit position; typically converges in 2-3 rounds).
// `removed` stays distributed: lane l owns word l. Rows KTOP..MROWS-1 are
// zero-padded in shared so all accesses stay in-bounds (R11 bug fix).
__global__ void k_nms_out(float* out) {
    extern __shared__ unsigned smask[];        // MROWS * MSTRIDE words
    __shared__ unsigned s_keep[32];
    __shared__ unsigned s_valid[32];

    int b   = blockIdx.x;
    int tid = threadIdx.x;

    // stage mask into shared with stride 33 (vector global loads, scalar STS)
    const uint4* mp4 = (const uint4*)(g_mask + (size_t)b * KTOP * 32);
    for (int i4 = tid; i4 < KTOP * 32 / 4; i4 += 1024) {
        uint4 v = mp4[i4];
        int gidx = i4 * 4;
        int row = gidx >> 5, word = gidx & 31;   // 4 words stay in one row
        unsigned* dst = &smask[row * MSTRIDE + word];
        dst[0] = v.x; dst[1] = v.y; dst[2] = v.z; dst[3] = v.w;
    }
    // zero-fill padding rows KTOP..MROWS-1 (in-bounds reads, never "kept")
    for (int i = KTOP * MSTRIDE + tid; i < MROWS * MSTRIDE; i += 1024)
        smask[i] = 0u;
    // valid words via batched loads + ballots
    if (tid < 32) {
        int lane = tid;
        float vsc[32];
#pragma unroll
        for (int w = 0; w < 32; w++) {
            int row = w * 32 + lane;
            vsc[w] = (row < KTOP) ? g_top_score[b * KTOP + row] : -1.0f;
        }
#pragma unroll
        for (int w = 0; w < 32; w++) {
            unsigned bal = __ballot_sync(0xffffffffu, vsc[w] >= SCORE_THR);
            if (lane == w) s_valid[w] = bal;
        }
    }
    __syncthreads();

    if (tid < 32) {
        int lane = tid;
        unsigned below = (1u << lane) - 1u;
        unsigned removedw = 0;                 // lane l: word l of removed

        for (int w = 0; w < 32; w++) {
            int rowbase = w * 32;
            // diag word: m[rowbase+lane][word w]  (conflict-free: stride 33)
            unsigned diag = smask[(rowbase + lane) * MSTRIDE + w];
            unsigned rw = __shfl_sync(0xffffffffu, removedw, w);
            unsigned cand = s_valid[w] & ~rw;

            unsigned K = cand;
            while (true) {
                bool sup = (K & below & diag) != 0u;
                unsigned Kn = cand & ~__ballot_sync(0xffffffffu, sup);
                if (Kn == K) break;
                K = Kn;
            }
            if (lane == w) s_keep[w] = K;

            // accumulate removed word `lane` over kept rows (4-way ILP)
            unsigned acc0 = 0, acc1 = 0, acc2 = 0, acc3 = 0;
#pragma unroll
            for (int q = 0; q < 32; q += 4) {
                acc0 |= smask[(rowbase + q + 0) * MSTRIDE + lane] & (unsigned)(-(int)((K >> (q + 0)) & 1u));
                acc1 |= smask[(rowbase + q + 1) * MSTRIDE + lane] & (unsigned)(-(int)((K >> (q + 1)) & 1u));
                acc2 |= smask[(rowbase + q + 2) * MSTRIDE + lane] & (unsigned)(-(int)((K >> (q + 2)) & 1u));
                acc3 |= smask[(rowbase + q + 3) * MSTRIDE + lane] & (unsigned)(-(int)((K >> (q + 3)) & 1u));
            }
            removedw |= (acc0 | acc1) | (acc2 | acc3);
        }
    }
    __syncthreads();

    for (int i = tid; i < KTOP; i += blockDim.x) {
        int g = b * KTOP + i;
        int keep = (s_keep[i >> 5] >> (i & 31)) & 1;

        float  s  = g_top_score[g];
        int    c  = g_top_cls[g];
        float4 bx = g_top_box[g];
        float x1 = fminf(fmaxf(bx.x, 0.0f), 1023.0f);
        float y1 = fminf(fmaxf(bx.y, 0.0f), 1023.0f);
        float x2 = fminf(fmaxf(bx.z, 0.0f), 1023.0f);
        float y2 = fminf(fmaxf(bx.w, 0.0f), 1023.0f);

        out[g]                = keep ? s : 0.0f;
        out[BATCH * KTOP + g] = keep ? (float)c : 0.0f;
        float* bo = out + 2 * BATCH * KTOP + (size_t)g * 4;
        bo[0] = keep ? x1 : 0.0f;
        bo[1] = keep ? y1 : 0.0f;
        bo[2] = keep ? x2 : 0.0f;
        bo[3] = keep ? y2 : 0.0f;
    }
}

// ---------------- launch ----------------------------------------------------
extern "C" void kernel_launch(void* const* d_in, const int* in_sizes, int n_in,
                              void* d_out, int out_size) {
    InPtrs P;
    for (int l = 0; l < 5; l++) { P.cls[l] = nullptr; P.cnt[l] = nullptr; P.reg[l] = nullptr; }
    bool seen131072 = false, seen32768 = false, seen8192 = false, seen2048 = false;

    for (int i = 0; i < n_in; i++) {
        const float* p = (const float*)d_in[i];
        switch (in_sizes[i]) {
            case 10485760: P.cls[0] = p; break;
            case 2621440:  P.cls[1] = p; break;
            case 655360:   P.cls[2] = p; break;
            case 163840:   P.cls[3] = p; break;
            case 40960:    P.cls[4] = p; break;
            case 524288:   P.reg[0] = p; break;
            case 512:      P.cnt[4] = p; break;
            case 131072:   if (!seen131072) { P.cnt[0] = p; seen131072 = true; } else P.reg[1] = p; break;
            case 32768:    if (!seen32768)  { P.cnt[1] = p; seen32768 = true; }  else P.reg[2] = p; break;
            case 8192:     if (!seen8192)   { P.cnt[2] = p; seen8192 = true; }   else P.reg[3] = p; break;
            case 2048:     if (!seen2048)   { P.cnt[3] = p; seen2048 = true; }   else P.reg[4] = p; break;
            default: break; // batch_imgs unused (shape only)
        }
    }

    static bool attr_set = false;
    if (!attr_set) {
        cudaFuncSetAttribute(k_nms_out, cudaFuncAttributeMaxDynamicSharedMemorySize,
                             MROWS * MSTRIDE * (int)sizeof(unsigned));
        attr_set = true;
    }

    dim3 gdec((NA / 4 + 255) / 256, BATCH);
    k_decode<<<gdec, 256>>>(P);
    k_topk_gather<<<BATCH, 1024>>>();
    k_mask<<<dim3(32, BATCH), 1024>>>();
    k_nms_out<<<BATCH, 1024, MROWS * MSTRIDE * sizeof(unsigned)>>>((float*)d_out);
    (void)out_size;
}

// round 14
// speedup vs baseline: 1.1836x; 1.0388x over previous
#include <cuda_runtime.h>
#include <math.h>

#define NA    21824      // total anchors per image
#define BATCH 8
#define NBINS 8192
#define KTOP  1000
#define SORTN 2048
#define IOU_THR 0.6f
#define SCORE_THR 0.05f

#define MROWS 1024            // mask rows staged (padded; rows >= KTOP zeroed)
#define MSTRIDE 33            // shared stride (conflict-free diagonal reads)

struct InPtrs {
    const float* cls[5];
    const float* cnt[5];
    const float* reg[5];
};

// ---------------- scratch (device globals; no allocation allowed) ----------
__device__ float    g_score[BATCH * NA];
__device__ int      g_cls  [BATCH * NA];
__device__ float4   g_box  [BATCH * NA];

__device__ int      g_top_idx  [BATCH * KTOP];
__device__ float    g_top_score[BATCH * KTOP];
__device__ int      g_top_cls  [BATCH * KTOP];
__device__ float4   g_top_box  [BATCH * KTOP];

__device__ float4   g_nx   [BATCH * KTOP];   // class-offset boxes
__device__ float    g_area [BATCH * KTOP];

__device__ __align__(16) unsigned g_mask [BATCH * KTOP * 32]; // suppression bitmask

// Bit-exact replica of XLA:CPU's GenerateVF32Exp (Cephes expf, unfused
// mul/add). Verified bit-exact against the reference in R6.
__device__ __forceinline__ float xla_cpu_expf(float v) {
    float x = fminf(fmaxf(v, -88.3762626647949f), 88.3762626647950f);
    float fx = floorf(__fadd_rn(__fmul_rn(x, 1.44269504088896341f), 0.5f));
    float tmp = __fmul_rn(0.693359375f, fx);
    float z   = __fmul_rn(-2.12194440e-4f, fx);
    float r   = __fsub_rn(__fsub_rn(x, tmp), z);
    z = __fmul_rn(r, r);
    float y = __fadd_rn(__fmul_rn(r, 1.9875691500E-4f), 1.3981999507E-3f);
    y = __fadd_rn(__fmul_rn(y, r), 8.3334519073E-3f);
    y = __fadd_rn(__fmul_rn(y, r), 4.1665795894E-2f);
    y = __fadd_rn(__fmul_rn(y, r), 1.6666665459E-1f);
    y = __fadd_rn(__fmul_rn(y, r), 5.0000001201E-1f);
    y = __fadd_rn(__fmul_rn(y, z), r);
    y = __fadd_rn(1.0f, y);
    int emm0 = ((int)fx + 0x7f) << 23;
    float p2n = __int_as_float(emm0);
    return fmaxf(__fmul_rn(y, p2n), v);
}

__device__ __forceinline__ float xla_sigmoid(float x) {
    return __fdiv_rn(1.0f, __fadd_rn(1.0f, xla_cpu_expf(-x)));
}

// ---------------- stage 1: per-anchor decode (4 anchors / thread) ----------
__global__ void k_decode(InPtrs p) {
    int v = blockIdx.x * blockDim.x + threadIdx.x;
    int b = blockIdx.y;
    if (v >= NA / 4) return;
    int a0 = v * 4;

    int l, base;
    if      (a0 < 16384) { l = 0; base = 0; }
    else if (a0 < 20480) { l = 1; base = 16384; }
    else if (a0 < 21504) { l = 2; base = 20480; }
    else if (a0 < 21760) { l = 3; base = 21504; }
    else                 { l = 4; base = 21760; }

    int local = a0 - base;
    int lw = 7 - l, hw = 1 << (2 * lw), s = 8 << l;
    int yy = local >> lw, xx = local & ((1 << lw) - 1);
    float cy  = (float)(yy * s + (s >> 1));
    float cx0 = (float)(xx * s + (s >> 1));
    float fs  = (float)s;

    const float*  cb  = p.cls[l] + (size_t)b * 80 * hw + local;
    const float4* cb4 = (const float4*)cb;
    int hw4 = hw >> 2;

    float m1[4], m2[4];
    int   i1[4];
    {
        float4 f = cb4[0];
        m1[0]=f.x; m1[1]=f.y; m1[2]=f.z; m1[3]=f.w;
#pragma unroll
        for (int k = 0; k < 4; k++) { m2[k] = -1e30f; i1[k] = 0; }
    }
#pragma unroll 8
    for (int c = 1; c < 80; c++) {
        float4 f = cb4[(size_t)c * hw4];
        float vv[4] = {f.x, f.y, f.z, f.w};
#pragma unroll
        for (int k = 0; k < 4; k++) {
            bool gt = vv[k] > m1[k];
            m2[k] = gt ? m1[k] : fmaxf(m2[k], vv[k]);
            i1[k] = gt ? c : i1[k];
            m1[k] = gt ? vv[k] : m1[k];
        }
    }

    float4 cn4 = *(const float4*)(p.cnt[l] + (size_t)b * hw + local);
    float cnt[4] = {cn4.x, cn4.y, cn4.z, cn4.w};

    const float* rb = p.reg[l] + (size_t)b * 4 * hw + local;
    float4 r0v = *(const float4*)(rb);
    float4 r1v = *(const float4*)(rb + (size_t)hw);
    float4 r2v = *(const float4*)(rb + (size_t)2 * hw);
    float4 r3v = *(const float4*)(rb + (size_t)3 * hw);
    float r0[4] = {r0v.x, r0v.y, r0v.z, r0v.w};
    float r1[4] = {r1v.x, r1v.y, r1v.z, r1v.w};
    float r2[4] = {r2v.x, r2v.y, r2v.z, r2v.w};
    float r3[4] = {r3v.x, r3v.y, r3v.z, r3v.w};

    float sc[4]; int cl[4];
#pragma unroll
    for (int k = 0; k < 4; k++) {
        float best; int bi;
        if (m1[k] <= 8.0f && m2[k] < __fadd_rn(m1[k], -1e-3f)) {
            best = xla_sigmoid(m1[k]);
            bi   = i1[k];
        } else {
            // exact reference semantics: first-wins argmax over sigmoids
            best = xla_sigmoid(cb[k]); bi = 0;
            for (int c = 1; c < 80; c++) {
                float t = xla_sigmoid(cb[(size_t)c * hw + k]);
                if (t > best) { best = t; bi = c; }
            }
        }
        sc[k] = __fsqrt_rn(__fmul_rn(best, xla_sigmoid(cnt[k])));
        cl[k] = bi + 1;
    }

    size_t o  = (size_t)b * NA + a0;
    ((float4*)g_score)[o >> 2] = make_float4(sc[0], sc[1], sc[2], sc[3]);
    ((int4*)g_cls)[o >> 2]     = make_int4(cl[0], cl[1], cl[2], cl[3]);
#pragma unroll
    for (int k = 0; k < 4; k++) {
        float cx = __fadd_rn(cx0, (float)k * fs);
        g_box[o + k] = make_float4(__fsub_rn(cx, r0[k]), __fsub_rn(cy, r1[k]),
                                   __fadd_rn(cx, r2[k]), __fadd_rn(cy, r3[k]));
    }
}

// ---------------- stage 2: exact top-1000 + gather (fused, per batch) ------
__global__ void k_topk_gather() {
    int b = blockIdx.x;
    int t = threadIdx.x;

    __shared__ unsigned hist[NBINS];               // 32KB
    __shared__ unsigned long long s_keys[SORTN];   // 16KB
    __shared__ unsigned s_part[1024];
    __shared__ int sT, sT2, sCntGt;
    __shared__ int s_nsel;

    const float* sp = g_score + (size_t)b * NA;

    for (int i = t; i < NBINS; i += 1024) hist[i] = 0;
    __syncthreads();
    for (int a = t; a < NA; a += 1024) {
        unsigned bits = __float_as_uint(sp[a]);
        atomicAdd(&hist[bits >> 17], 1u);
    }
    __syncthreads();

    {
        int base = t * 8;
        unsigned loc[8], csum = 0;
#pragma unroll
        for (int q = 0; q < 8; q++) { loc[q] = hist[base + q]; csum += loc[q]; }
        s_part[t] = csum;
        __syncthreads();
        for (int o = 1; o < 1024; o <<= 1) {
            unsigned add = (t + o < 1024) ? s_part[t + o] : 0u;
            __syncthreads();
            s_part[t] += add;
            __syncthreads();
        }
        unsigned inc = s_part[t];
        unsigned exc = inc - csum;
        if (exc < KTOP && inc >= KTOP) {
            unsigned run = exc;
            for (int q = 7; q >= 0; q--) {
                unsigned nxt = run + loc[q];
                if (nxt >= KTOP) { sT = base + q; sCntGt = (int)run; break; }
                run = nxt;
            }
        }
    }
    __syncthreads();
    unsigned T = (unsigned)sT;
    int k2 = KTOP - sCntGt;

    for (int i = t; i < NBINS; i += 1024) hist[i] = 0;
    __syncthreads();
    for (int a = t; a < NA; a += 1024) {
        unsigned bits = __float_as_uint(sp[a]);
        if ((bits >> 17) == T)
            atomicAdd(&hist[(bits >> 4) & 0x1FFFu], 1u);
    }
    __syncthreads();
    {
        int base = t * 8;
        unsigned loc[8], csum = 0;
#pragma unroll
        for (int q = 0; q < 8; q++) { loc[q] = hist[base + q]; csum += loc[q]; }
        s_part[t] = csum;
        __syncthreads();
        for (int o = 1; o < 1024; o <<= 1) {
            unsigned add = (t + o < 1024) ? s_part[t + o] : 0u;
            __syncthreads();
            s_part[t] += add;
            __syncthreads();
        }
        unsigned inc = s_part[t];
        unsigned exc = inc - csum;
        if ((int)exc < k2 && (int)inc >= k2) {
            unsigned run = exc;
            for (int q = 7; q >= 0; q--) {
                run += loc[q];
                if ((int)run >= k2) { sT2 = base + q; break; }
            }
        }
        if (t == 0) s_nsel = 0;
    }
    __syncthreads();
    unsigned T2 = (unsigned)sT2;

    // ---- compact candidates (no pre-zero; pad after count known) ----
    for (int a = t; a < NA; a += 1024) {
        unsigned bits = __float_as_uint(sp[a]);
        unsigned hb = bits >> 17;
        bool cand = (hb > T) || (hb == T && ((bits >> 4) & 0x1FFFu) >= T2);
        if (cand) {
            int pos = atomicAdd(&s_nsel, 1);
            if (pos < SORTN)
                s_keys[pos] = ((unsigned long long)bits << 32) |
                              (unsigned)(0xFFFFFFFFu - (unsigned)a);
        }
    }
    __syncthreads();

    // ---- dynamic-size bitonic sort: 1024 nearly always (n ~= 1000-1010) ---
    int n = min(s_nsel, SORTN);
    int SN = (n <= 1024) ? 1024 : SORTN;
    for (int i = n + t; i < SN; i += 1024) s_keys[i] = 0ULL;  // pad with 0
    __syncthreads();

    for (int k = 2; k <= SN; k <<= 1) {
        for (int j = k >> 1; j > 0; j >>= 1) {
            for (int e = t; e < SN; e += 1024) {
                int pr = e ^ j;
                if (pr > e) {
                    unsigned long long A = s_keys[e], Bv = s_keys[pr];
                    bool up = ((e & k) == 0);
                    if ((A > Bv) == up) { s_keys[e] = Bv; s_keys[pr] = A; }
                }
            }
            __syncthreads();
        }
    }

    // ---- gather payload + maxc + offset boxes (fused) ----
    float  m = -1e30f;
    float4 box = make_float4(0.f, 0.f, 0.f, 0.f);
    int    cls = 0;
    if (t < KTOP) {
        unsigned long long key = s_keys[SN - 1 - t];
        unsigned bits = (unsigned)(key >> 32);
        int a = (int)(0xFFFFFFFFu - (unsigned)key);
        g_top_idx[b * KTOP + t]   = a;
        g_top_score[b * KTOP + t] = __uint_as_float(bits);
        box = g_box[(size_t)b * NA + a];
        cls = g_cls[(size_t)b * NA + a];
        g_top_box[b * KTOP + t] = box;
        g_top_cls[b * KTOP + t] = cls;
        m = fmaxf(fmaxf(box.x, box.y), fmaxf(box.z, box.w));
    }
    __syncthreads();
    float* s_red = (float*)s_part;
    s_red[t] = m;
    __syncthreads();
    for (int o = 512; o > 0; o >>= 1) {
        if (t < o) s_red[t] = fmaxf(s_red[t], s_red[t + o]);
        __syncthreads();
    }
    float maxc = s_red[0];

    if (t < KTOP) {
        float off = __fmul_rn((float)cls, __fadd_rn(maxc, 1.0f));
        float x1 = __fadd_rn(box.x, off), y1 = __fadd_rn(box.y, off);
        float x2 = __fadd_rn(box.z, off), y2 = __fadd_rn(box.w, off);
        g_nx[b * KTOP + t]   = make_float4(x1, y1, x2, y2);
        g_area[b * KTOP + t] = __fmul_rn(__fadd_rn(__fsub_rn(x2, x1), 1.0f),
                                         __fadd_rn(__fsub_rn(y2, y1), 1.0f));
    }
}

// ---------------- stage 3: suppression bitmask — upper triangle only -------
__global__ void k_mask() {
    int b    = blockIdx.y;
    int gx   = blockIdx.x;
    int tid  = threadIdx.x;
    int warp = tid >> 5;
    int lane = tid & 31;

    __shared__ float sx1[KTOP], sy1[KTOP], sx2[KTOP], sy2[KTOP], sa[KTOP];
    for (int i = tid; i < KTOP; i += 1024) {
        float4 v = g_nx[b * KTOP + i];
        sx1[i] = v.x; sy1[i] = v.y; sx2[i] = v.z; sy2[i] = v.w;
        sa[i]  = g_area[b * KTOP + i];
    }
    __syncthreads();

    int i = gx * 32 + warp;
    if (i >= KTOP) return;

    float x1 = sx1[i], y1 = sy1[i], x2 = sx2[i], y2 = sy2[i], ar = sa[i];
    unsigned myword = 0;
    for (int g = gx; g < 32; g++) {
        int j = g * 32 + lane;
        bool sup = false;
        if (j < KTOP) {
            float xx1 = fmaxf(x1, sx1[j]);
            float yy1 = fmaxf(y1, sy1[j]);
            float xx2 = fminf(x2, sx2[j]);
            float yy2 = fminf(y2, sy2[j]);
            float inter = __fmul_rn(fmaxf(__fsub_rn(xx2, xx1), 0.0f),
                                    fmaxf(__fsub_rn(yy2, yy1), 0.0f));
            float denom = __fsub_rn(__fadd_rn(ar, sa[j]), inter);
            sup = __fdiv_rn(inter, denom) > IOU_THR;
        }
        unsigned bal = __ballot_sync(0xffffffffu, sup);
        if (lane == g) myword = bal;
    }
    if (lane >= gx)
        g_mask[((size_t)b * KTOP + i) * 32 + lane] = myword;
}

// ---------------- stage 4+5: warp-parallel fixpoint NMS + output -----------
// Symmetric IoU => diagonal-block columns equal rows: lane q's suppression
// column within the 32x32 diagonal block is row (w*32+q)'s word w (one LDS,
// stride-33 => conflict-free). Greedy NMS within a word is the UNIQUE
// fixpoint of  K' = cand & ~ballot( K & below(q) & diag_q != 0 ).
// `removed` stays distributed: lane l owns word l. Rows KTOP..MROWS-1 are
// zero-padded in shared so all accesses stay in-bounds.
__global__ void k_nms_out(float* out) {
    extern __shared__ unsigned smask[];        // MROWS * MSTRIDE words
    __shared__ unsigned s_keep[32];
    __shared__ unsigned s_valid[32];

    int b   = blockIdx.x;
    int tid = threadIdx.x;

    // stage mask into shared with stride 33 (vector global loads, scalar STS)
    const uint4* mp4 = (const uint4*)(g_mask + (size_t)b * KTOP * 32);
    for (int i4 = tid; i4 < KTOP * 32 / 4; i4 += 1024) {
        uint4 v = mp4[i4];
        int gidx = i4 * 4;
        int row = gidx >> 5, word = gidx & 31;   // 4 words stay in one row
        unsigned* dst = &smask[row * MSTRIDE + word];
        dst[0] = v.x; dst[1] = v.y; dst[2] = v.z; dst[3] = v.w;
    }
    // zero-fill padding rows KTOP..MROWS-1 (in-bounds reads, never "kept")
    for (int i = KTOP * MSTRIDE + tid; i < MROWS * MSTRIDE; i += 1024)
        smask[i] = 0u;
    // valid words via batched loads + ballots
    if (tid < 32) {
        int lane = tid;
        float vsc[32];
#pragma unroll
        for (int w = 0; w < 32; w++) {
            int row = w * 32 + lane;
            vsc[w] = (row < KTOP) ? g_top_score[b * KTOP + row] : -1.0f;
        }
#pragma unroll
        for (int w = 0; w < 32; w++) {
            unsigned bal = __ballot_sync(0xffffffffu, vsc[w] >= SCORE_THR);
            if (lane == w) s_valid[w] = bal;
        }
    }
    __syncthreads();

    if (tid < 32) {
        int lane = tid;
        unsigned below = (1u << lane) - 1u;
        unsigned removedw = 0;                 // lane l: word l of removed

        for (int w = 0; w < 32; w++) {
            int rowbase = w * 32;
            // diag word: m[rowbase+lane][word w]  (conflict-free: stride 33)
            unsigned diag = smask[(rowbase + lane) * MSTRIDE + w];
            unsigned rw = __shfl_sync(0xffffffffu, removedw, w);
            unsigned cand = s_valid[w] & ~rw;

            unsigned K = cand;
            while (true) {
                bool sup = (K & below & diag) != 0u;
                unsigned Kn = cand & ~__ballot_sync(0xffffffffu, sup);
                if (Kn == K) break;
                K = Kn;
            }
            if (lane == w) s_keep[w] = K;

            // accumulate removed word `lane` over kept rows (4-way ILP)
            unsigned acc0 = 0, acc1 = 0, acc2 = 0, acc3 = 0;
#pragma unroll
            for (int q = 0; q < 32; q += 4) {
                acc0 |= smask[(rowbase + q + 0) * MSTRIDE + lane] & (unsigned)(-(int)((K >> (q + 0)) & 1u));
                acc1 |= smask[(rowbase + q + 1) * MSTRIDE + lane] & (unsigned)(-(int)((K >> (q + 1)) & 1u));
                acc2 |= smask[(rowbase + q + 2) * MSTRIDE + lane] & (unsigned)(-(int)((K >> (q + 2)) & 1u));
                acc3 |= smask[(rowbase + q + 3) * MSTRIDE + lane] & (unsigned)(-(int)((K >> (q + 3)) & 1u));
            }
            removedw |= (acc0 | acc1) | (acc2 | acc3);
        }
    }
    __syncthreads();

    for (int i = tid; i < KTOP; i += blockDim.x) {
        int g = b * KTOP + i;
        int keep = (s_keep[i >> 5] >> (i & 31)) & 1;

        float  s  = g_top_score[g];
        int    c  = g_top_cls[g];
        float4 bx = g_top_box[g];
        float x1 = fminf(fmaxf(bx.x, 0.0f), 1023.0f);
        float y1 = fminf(fmaxf(bx.y, 0.0f), 1023.0f);
        float x2 = fminf(fmaxf(bx.z, 0.0f), 1023.0f);
        float y2 = fminf(fmaxf(bx.w, 0.0f), 1023.0f);

        out[g]                = keep ? s : 0.0f;
        out[BATCH * KTOP + g] = keep ? (float)c : 0.0f;
        float* bo = out + 2 * BATCH * KTOP + (size_t)g * 4;
        bo[0] = keep ? x1 : 0.0f;
        bo[1] = keep ? y1 : 0.0f;
        bo[2] = keep ? x2 : 0.0f;
        bo[3] = keep ? y2 : 0.0f;
    }
}

// ---------------- launch ----------------------------------------------------
extern "C" void kernel_launch(void* const* d_in, const int* in_sizes, int n_in,
                              void* d_out, int out_size) {
    InPtrs P;
    for (int l = 0; l < 5; l++) { P.cls[l] = nullptr; P.cnt[l] = nullptr; P.reg[l] = nullptr; }
    bool seen131072 = false, seen32768 = false, seen8192 = false, seen2048 = false;

    for (int i = 0; i < n_in; i++) {
        const float* p = (const float*)d_in[i];
        switch (in_sizes[i]) {
            case 10485760: P.cls[0] = p; break;
            case 2621440:  P.cls[1] = p; break;
            case 655360:   P.cls[2] = p; break;
            case 163840:   P.cls[3] = p; break;
            case 40960:    P.cls[4] = p; break;
            case 524288:   P.reg[0] = p; break;
            case 512:      P.cnt[4] = p; break;
            case 131072:   if (!seen131072) { P.cnt[0] = p; seen131072 = true; } else P.reg[1] = p; break;
            case 32768:    if (!seen32768)  { P.cnt[1] = p; seen32768 = true; }  else P.reg[2] = p; break;
            case 8192:     if (!seen8192)   { P.cnt[2] = p; seen8192 = true; }   else P.reg[3] = p; break;
            case 2048:     if (!seen2048)   { P.cnt[3] = p; seen2048 = true; }   else P.reg[4] = p; break;
            default: break; // batch_imgs unused (shape only)
        }
    }

    static bool attr_set = false;
    if (!attr_set) {
        cudaFuncSetAttribute(k_nms_out, cudaFuncAttributeMaxDynamicSharedMemorySize,
                             MROWS * MSTRIDE * (int)sizeof(unsigned));
        attr_set = true;
    }

    dim3 gdec((NA / 4 + 255) / 256, BATCH);
    k_decode<<<gdec, 256>>>(P);
    k_topk_gather<<<BATCH, 1024>>>();
    k_mask<<<dim3(32, BATCH), 1024>>>();
    k_nms_out<<<BATCH, 1024, MROWS * MSTRIDE * sizeof(unsigned)>>>((float*)d_out);
    (void)out_size;
}

// round 17
// speedup vs baseline: 1.3014x; 1.0995x over previous
#include <cuda_runtime.h>
#include <math.h>

#define NA    21824      // total anchors per image
#define BATCH 8
#define NBINS 8192
#define KTOP  1000
#define SORTN 2048
#define IOU_THR 0.6f
#define SCORE_THR 0.05f

#define MROWS 1024            // mask rows staged (padded; rows >= KTOP zeroed)
#define MSTRIDE 33            // shared stride (conflict-free diagonal reads)

struct InPtrs {
    const float* cls[5];
    const float* cnt[5];
    const float* reg[5];
};

// ---------------- scratch (device globals; no allocation allowed) ----------
__device__ float    g_score[BATCH * NA];
__device__ int      g_cls  [BATCH * NA];
__device__ float4   g_box  [BATCH * NA];

__device__ int      g_top_idx  [BATCH * KTOP];
__device__ float    g_top_score[BATCH * KTOP];
__device__ int      g_top_cls  [BATCH * KTOP];
__device__ float4   g_top_box  [BATCH * KTOP];

__device__ float4   g_nx   [BATCH * KTOP];   // class-offset boxes
__device__ float    g_area [BATCH * KTOP];

__device__ __align__(16) unsigned g_mask [BATCH * KTOP * 32]; // suppression bitmask

// Bit-exact replica of XLA:CPU's GenerateVF32Exp (Cephes expf, unfused
// mul/add). Verified bit-exact against the reference in R6.
__device__ __forceinline__ float xla_cpu_expf(float v) {
    float x = fminf(fmaxf(v, -88.3762626647949f), 88.3762626647950f);
    float fx = floorf(__fadd_rn(__fmul_rn(x, 1.44269504088896341f), 0.5f));
    float tmp = __fmul_rn(0.693359375f, fx);
    float z   = __fmul_rn(-2.12194440e-4f, fx);
    float r   = __fsub_rn(__fsub_rn(x, tmp), z);
    z = __fmul_rn(r, r);
    float y = __fadd_rn(__fmul_rn(r, 1.9875691500E-4f), 1.3981999507E-3f);
    y = __fadd_rn(__fmul_rn(y, r), 8.3334519073E-3f);
    y = __fadd_rn(__fmul_rn(y, r), 4.1665795894E-2f);
    y = __fadd_rn(__fmul_rn(y, r), 1.6666665459E-1f);
    y = __fadd_rn(__fmul_rn(y, r), 5.0000001201E-1f);
    y = __fadd_rn(__fmul_rn(y, z), r);
    y = __fadd_rn(1.0f, y);
    int emm0 = ((int)fx + 0x7f) << 23;
    float p2n = __int_as_float(emm0);
    return fmaxf(__fmul_rn(y, p2n), v);
}

__device__ __forceinline__ float xla_sigmoid(float x) {
    return __fdiv_rn(1.0f, __fadd_rn(1.0f, xla_cpu_expf(-x)));
}

// Block-wide inclusive SUFFIX sum (sum over threads >= t). 2 barriers.
// s_warp needs >= 32 unsigned slots.
__device__ __forceinline__ unsigned block_suffix_incl(unsigned csum,
                                                      unsigned* s_warp, int tid) {
    int lane = tid & 31, wid = tid >> 5;
    unsigned x = csum;
#pragma unroll
    for (int off = 1; off < 32; off <<= 1) {
        unsigned y = __shfl_down_sync(0xffffffffu, x, off);
        if (lane + off < 32) x += y;
    }
    if (lane == 0) s_warp[wid] = x;       // warp total (suffix from lane 0)
    __syncthreads();
    if (tid < 32) {
        unsigned w = s_warp[tid];
        unsigned xx = w;
#pragma unroll
        for (int off = 1; off < 32; off <<= 1) {
            unsigned y = __shfl_down_sync(0xffffffffu, xx, off);
            if (tid + off < 32) xx += y;
        }
        s_warp[tid] = xx - w;             // exclusive suffix (warps > tid)
    }
    __syncthreads();
    return x + s_warp[wid];
}

// register-level bitonic compare-exchange via shfl (partner in-warp, j<=16)
__device__ __forceinline__ unsigned long long bitonic_shfl_step(
    unsigned long long v, int t, int k, int j) {
    unsigned long long pv = __shfl_xor_sync(0xffffffffu, v, j);
    bool up = ((t & k) == 0);
    bool lower = ((t & j) == 0);
    bool takeMax = (lower != up);
    unsigned long long mn = v < pv ? v : pv;
    unsigned long long mx = v < pv ? pv : v;
    return takeMax ? mx : mn;
}

// ---------------- stage 1: per-anchor decode (4 anchors / thread) ----------
__global__ void k_decode(InPtrs p) {
    int v = blockIdx.x * blockDim.x + threadIdx.x;
    int b = blockIdx.y;
    if (v >= NA / 4) return;
    int a0 = v * 4;

    int l, base;
    if      (a0 < 16384) { l = 0; base = 0; }
    else if (a0 < 20480) { l = 1; base = 16384; }
    else if (a0 < 21504) { l = 2; base = 20480; }
    else if (a0 < 21760) { l = 3; base = 21504; }
    else                 { l = 4; base = 21760; }

    int local = a0 - base;
    int lw = 7 - l, hw = 1 << (2 * lw), s = 8 << l;
    int yy = local >> lw, xx = local & ((1 << lw) - 1);
    float cy  = (float)(yy * s + (s >> 1));
    float cx0 = (float)(xx * s + (s >> 1));
    float fs  = (float)s;

    const float*  cb  = p.cls[l] + (size_t)b * 80 * hw + local;
    const float4* cb4 = (const float4*)cb;
    int hw4 = hw >> 2;

    float m1[4], m2[4];
    int   i1[4];
    {
        float4 f = cb4[0];
        m1[0]=f.x; m1[1]=f.y; m1[2]=f.z; m1[3]=f.w;
#pragma unroll
        for (int k = 0; k < 4; k++) { m2[k] = -1e30f; i1[k] = 0; }
    }
#pragma unroll 8
    for (int c = 1; c < 80; c++) {
        float4 f = cb4[(size_t)c * hw4];
        float vv[4] = {f.x, f.y, f.z, f.w};
#pragma unroll
        for (int k = 0; k < 4; k++) {
            bool gt = vv[k] > m1[k];
            m2[k] = gt ? m1[k] : fmaxf(m2[k], vv[k]);
            i1[k] = gt ? c : i1[k];
            m1[k] = gt ? vv[k] : m1[k];
        }
    }

    float4 cn4 = *(const float4*)(p.cnt[l] + (size_t)b * hw + local);
    float cnt[4] = {cn4.x, cn4.y, cn4.z, cn4.w};

    const float* rb = p.reg[l] + (size_t)b * 4 * hw + local;
    float4 r0v = *(const float4*)(rb);
    float4 r1v = *(const float4*)(rb + (size_t)hw);
    float4 r2v = *(const float4*)(rb + (size_t)2 * hw);
    float4 r3v = *(const float4*)(rb + (size_t)3 * hw);
    float r0[4] = {r0v.x, r0v.y, r0v.z, r0v.w};
    float r1[4] = {r1v.x, r1v.y, r1v.z, r1v.w};
    float r2[4] = {r2v.x, r2v.y, r2v.z, r2v.w};
    float r3[4] = {r3v.x, r3v.y, r3v.z, r3v.w};

    float sc[4]; int cl[4];
#pragma unroll
    for (int k = 0; k < 4; k++) {
        float best; int bi;
        if (m1[k] <= 8.0f && m2[k] < __fadd_rn(m1[k], -1e-3f)) {
            best = xla_sigmoid(m1[k]);
            bi   = i1[k];
        } else {
            // exact reference semantics: first-wins argmax over sigmoids
            best = xla_sigmoid(cb[k]); bi = 0;
            for (int c = 1; c < 80; c++) {
                float t = xla_sigmoid(cb[(size_t)c * hw + k]);
                if (t > best) { best = t; bi = c; }
            }
        }
        sc[k] = __fsqrt_rn(__fmul_rn(best, xla_sigmoid(cnt[k])));
        cl[k] = bi + 1;
    }

    size_t o  = (size_t)b * NA + a0;
    ((float4*)g_score)[o >> 2] = make_float4(sc[0], sc[1], sc[2], sc[3]);
    ((int4*)g_cls)[o >> 2]     = make_int4(cl[0], cl[1], cl[2], cl[3]);
#pragma unroll
    for (int k = 0; k < 4; k++) {
        float cx = __fadd_rn(cx0, (float)k * fs);
        g_box[o + k] = make_float4(__fsub_rn(cx, r0[k]), __fsub_rn(cy, r1[k]),
                                   __fadd_rn(cx, r2[k]), __fadd_rn(cy, r3[k]));
    }
}

// ---------------- stage 2: exact top-1000 + gather (fused, per batch) ------
__global__ void k_topk_gather() {
    int b = blockIdx.x;
    int t = threadIdx.x;
    int lane = t & 31, wid = t >> 5;

    __shared__ unsigned hist[NBINS];               // 32KB
    __shared__ unsigned long long s_keys[SORTN];   // 16KB
    __shared__ unsigned s_warp[32];
    __shared__ float s_red[32];
    __shared__ int sT, sT2, sCntGt;
    __shared__ int s_nsel;

    const float* sp = g_score + (size_t)b * NA;

    for (int i = t; i < NBINS; i += 1024) hist[i] = 0;
    __syncthreads();
    for (int a = t; a < NA; a += 1024) {
        unsigned bits = __float_as_uint(sp[a]);
        atomicAdd(&hist[bits >> 17], 1u);
    }
    __syncthreads();

    {
        int base = t * 8;
        unsigned loc[8], csum = 0;
#pragma unroll
        for (int q = 0; q < 8; q++) { loc[q] = hist[base + q]; csum += loc[q]; }
        unsigned inc = block_suffix_incl(csum, s_warp, t);
        unsigned exc = inc - csum;
        if (exc < KTOP && inc >= KTOP) {
            unsigned run = exc;
            for (int q = 7; q >= 0; q--) {
                unsigned nxt = run + loc[q];
                if (nxt >= KTOP) { sT = base + q; sCntGt = (int)run; break; }
                run = nxt;
            }
        }
    }
    __syncthreads();
    unsigned T = (unsigned)sT;
    int k2 = KTOP - sCntGt;

    for (int i = t; i < NBINS; i += 1024) hist[i] = 0;
    __syncthreads();
    for (int a = t; a < NA; a += 1024) {
        unsigned bits = __float_as_uint(sp[a]);
        if ((bits >> 17) == T)
            atomicAdd(&hist[(bits >> 4) & 0x1FFFu], 1u);
    }
    __syncthreads();
    {
        int base = t * 8;
        unsigned loc[8], csum = 0;
#pragma unroll
        for (int q = 0; q < 8; q++) { loc[q] = hist[base + q]; csum += loc[q]; }
        unsigned inc = block_suffix_incl(csum, s_warp, t);
        unsigned exc = inc - csum;
        if ((int)exc < k2 && (int)inc >= k2) {
            unsigned run = exc;
            for (int q = 7; q >= 0; q--) {
                run += loc[q];
                if ((int)run >= k2) { sT2 = base + q; break; }
            }
        }
        if (t == 0) s_nsel = 0;
    }
    __syncthreads();
    unsigned T2 = (unsigned)sT2;

    // ---- compact candidates (no pre-zero; pad after count known) ----
    for (int a = t; a < NA; a += 1024) {
        unsigned bits = __float_as_uint(sp[a]);
        unsigned hb = bits >> 17;
        bool cand = (hb > T) || (hb == T && ((bits >> 4) & 0x1FFFu) >= T2);
        if (cand) {
            int pos = atomicAdd(&s_nsel, 1);
            if (pos < SORTN)
                s_keys[pos] = ((unsigned long long)bits << 32) |
                              (unsigned)(0xFFFFFFFFu - (unsigned)a);
        }
    }
    __syncthreads();

    int n = min(s_nsel, SORTN);
    int SN;
    if (n <= 1024) {
        // ---- hybrid bitonic sort of 1024: shfl for j<=16, shared for j>=32 --
        SN = 1024;
        if (t >= n) s_keys[t] = 0ULL;   // pad
        __syncthreads();
        unsigned long long v = s_keys[t];
#pragma unroll
        for (int k = 2; k <= 32; k <<= 1)
#pragma unroll
            for (int j = k >> 1; j >= 1; j >>= 1)
                v = bitonic_shfl_step(v, t, k, j);
        for (int k = 64; k <= 1024; k <<= 1) {
            s_keys[t] = v;
            __syncthreads();
            for (int j = k >> 1; j >= 32; j >>= 1) {
                int pr = t ^ j;
                if (pr > t) {
                    unsigned long long A = s_keys[t], Bv = s_keys[pr];
                    bool up = ((t & k) == 0);
                    if ((A > Bv) == up) { s_keys[t] = Bv; s_keys[pr] = A; }
                }
                __syncthreads();
            }
            v = s_keys[t];
#pragma unroll
            for (int j = 16; j >= 1; j >>= 1)
                v = bitonic_shfl_step(v, t, k, j);
            // safe: only own slot written next iter / below, after this point
        }
        s_keys[t] = v;
        __syncthreads();
    } else {
        // ---- rare fallback: generic 2048 shared bitonic ----
        SN = SORTN;
        for (int i = n + t; i < SN; i += 1024) s_keys[i] = 0ULL;
        __syncthreads();
        for (int k = 2; k <= SN; k <<= 1) {
            for (int j = k >> 1; j > 0; j >>= 1) {
                for (int e = t; e < SN; e += 1024) {
                    int pr = e ^ j;
                    if (pr > e) {
                        unsigned long long A = s_keys[e], Bv = s_keys[pr];
                        bool up = ((e & k) == 0);
                        if ((A > Bv) == up) { s_keys[e] = Bv; s_keys[pr] = A; }
                    }
                }
                __syncthreads();
            }
        }
    }

    // ---- gather payload + maxc + offset boxes (fused) ----
    float  m = -1e30f;
    float4 box = make_float4(0.f, 0.f, 0.f, 0.f);
    int    cls = 0;
    if (t < KTOP) {
        unsigned long long key = s_keys[SN - 1 - t];
        unsigned bits = (unsigned)(key >> 32);
        int a = (int)(0xFFFFFFFFu - (unsigned)key);
        g_top_idx[b * KTOP + t]   = a;
        g_top_score[b * KTOP + t] = __uint_as_float(bits);
        box = g_box[(size_t)b * NA + a];
        cls = g_cls[(size_t)b * NA + a];
        g_top_box[b * KTOP + t] = box;
        g_top_cls[b * KTOP + t] = cls;
        m = fmaxf(fmaxf(box.x, box.y), fmaxf(box.z, box.w));
    }
#pragma unroll
    for (int off = 16; off >= 1; off >>= 1)
        m = fmaxf(m, __shfl_xor_sync(0xffffffffu, m, off));
    if (lane == 0) s_red[wid] = m;
    __syncthreads();
    if (t < 32) {
        float mm = s_red[t];
#pragma unroll
        for (int off = 16; off >= 1; off >>= 1)
            mm = fmaxf(mm, __shfl_xor_sync(0xffffffffu, mm, off));
        if (t == 0) s_red[0] = mm;
    }
    __syncthreads();
    float maxc = s_red[0];

    if (t < KTOP) {
        float off = __fmul_rn((float)cls, __fadd_rn(maxc, 1.0f));
        float x1 = __fadd_rn(box.x, off), y1 = __fadd_rn(box.y, off);
        float x2 = __fadd_rn(box.z, off), y2 = __fadd_rn(box.w, off);
        g_nx[b * KTOP + t]   = make_float4(x1, y1, x2, y2);
        g_area[b * KTOP + t] = __fmul_rn(__fadd_rn(__fsub_rn(x2, x1), 1.0f),
                                         __fadd_rn(__fsub_rn(y2, y1), 1.0f));
    }
}

// ---------------- stage 3: suppression bitmask — upper triangle only -------
__global__ void k_mask() {
    int b    = blockIdx.y;
    int gx   = blockIdx.x;
    int tid  = threadIdx.x;
    int warp = tid >> 5;
    int lane = tid & 31;

    __shared__ float sx1[KTOP], sy1[KTOP], sx2[KTOP], sy2[KTOP], sa[KTOP];
    for (int i = tid; i < KTOP; i += 1024) {
        float4 v = g_nx[b * KTOP + i];
        sx1[i] = v.x; sy1[i] = v.y; sx2[i] = v.z; sy2[i] = v.w;
        sa[i]  = g_area[b * KTOP + i];
    }
    __syncthreads();

    int i = gx * 32 + warp;
    if (i >= KTOP) return;

    float x1 = sx1[i], y1 = sy1[i], x2 = sx2[i], y2 = sy2[i], ar = sa[i];
    unsigned myword = 0;
    for (int g = gx; g < 32; g++) {
        int j = g * 32 + lane;
        bool sup = false;
        if (j < KTOP) {
            float xx1 = fmaxf(x1, sx1[j]);
            float yy1 = fmaxf(y1, sy1[j]);
            float xx2 = fminf(x2, sx2[j]);
            float yy2 = fminf(y2, sy2[j]);
            float inter = __fmul_rn(fmaxf(__fsub_rn(xx2, xx1), 0.0f),
                                    fmaxf(__fsub_rn(yy2, yy1), 0.0f));
            float denom = __fsub_rn(__fadd_rn(ar, sa[j]), inter);
            sup = __fdiv_rn(inter, denom) > IOU_THR;
        }
        unsigned bal = __ballot_sync(0xffffffffu, sup);
        if (lane == g) myword = bal;
    }
    if (lane >= gx)
        g_mask[((size_t)b * KTOP + i) * 32 + lane] = myword;
}

// ---------------- stage 4+5: warp-parallel fixpoint NMS + output -----------
__global__ void k_nms_out(float* out) {
    extern __shared__ unsigned smask[];        // MROWS * MSTRIDE words
    __shared__ unsigned s_keep[32];
    __shared__ unsigned s_valid[32];

    int b   = blockIdx.x;
    int tid = threadIdx.x;

    const uint4* mp4 = (const uint4*)(g_mask + (size_t)b * KTOP * 32);
    for (int i4 = tid; i4 < KTOP * 32 / 4; i4 += 1024) {
        uint4 v = mp4[i4];
        int gidx = i4 * 4;
        int row = gidx >> 5, word = gidx & 31;
        unsigned* dst = &smask[row * MSTRIDE + word];
        dst[0] = v.x; dst[1] = v.y; dst[2] = v.z; dst[3] = v.w;
    }
    for (int i = KTOP * MSTRIDE + tid; i < MROWS * MSTRIDE; i += 1024)
        smask[i] = 0u;
    if (tid < 32) {
        int lane = tid;
        float vsc[32];
#pragma unroll
        for (int w = 0; w < 32; w++) {
            int row = w * 32 + lane;
            vsc[w] = (row < KTOP) ? g_top_score[b * KTOP + row] : -1.0f;
        }
#pragma unroll
        for (int w = 0; w < 32; w++) {
            unsigned bal = __ballot_sync(0xffffffffu, vsc[w] >= SCORE_THR);
            if (lane == w) s_valid[w] = bal;
        }
    }
    __syncthreads();

    if (tid < 32) {
        int lane = tid;
        unsigned below = (1u << lane) - 1u;
        unsigned removedw = 0;

        for (int w = 0; w < 32; w++) {
            int rowbase = w * 32;
            unsigned diag = smask[(rowbase + lane) * MSTRIDE + w];
            unsigned rw = __shfl_sync(0xffffffffu, removedw, w);
            unsigned cand = s_valid[w] & ~rw;

            unsigned K = cand;
            while (true) {
                bool sup = (K & below & diag) != 0u;
                unsigned Kn = cand & ~__ballot_sync(0xffffffffu, sup);
                if (Kn == K) break;
                K = Kn;
            }
            if (lane == w) s_keep[w] = K;

            unsigned acc0 = 0, acc1 = 0, acc2 = 0, acc3 = 0;
#pragma unroll
            for (int q = 0; q < 32; q += 4) {
                acc0 |= smask[(rowbase + q + 0) * MSTRIDE + lane] & (unsigned)(-(int)((K >> (q + 0)) & 1u));
                acc1 |= smask[(rowbase + q + 1) * MSTRIDE + lane] & (unsigned)(-(int)((K >> (q + 1)) & 1u));
                acc2 |= smask[(rowbase + q + 2) * MSTRIDE + lane] & (unsigned)(-(int)((K >> (q + 2)) & 1u));
                acc3 |= smask[(rowbase + q + 3) * MSTRIDE + lane] & (unsigned)(-(int)((K >> (q + 3)) & 1u));
            }
            removedw |= (acc0 | acc1) | (acc2 | acc3);
        }
    }
    __syncthreads();

    for (int i = tid; i < KTOP; i += blockDim.x) {
        int g = b * KTOP + i;
        int keep = (s_keep[i >> 5] >> (i & 31)) & 1;

        float  s  = g_top_score[g];
        int    c  = g_top_cls[g];
        float4 bx = g_top_box[g];
        float x1 = fminf(fmaxf(bx.x, 0.0f), 1023.0f);
        float y1 = fminf(fmaxf(bx.y, 0.0f), 1023.0f);
        float x2 = fminf(fmaxf(bx.z, 0.0f), 1023.0f);
        float y2 = fminf(fmaxf(bx.w, 0.0f), 1023.0f);

        out[g]                = keep ? s : 0.0f;
        out[BATCH * KTOP + g] = keep ? (float)c : 0.0f;
        float* bo = out + 2 * BATCH * KTOP + (size_t)g * 4;
        bo[0] = keep ? x1 : 0.0f;
        bo[1] = keep ? y1 : 0.0f;
        bo[2] = keep ? x2 : 0.0f;
        bo[3] = keep ? y2 : 0.0f;
    }
}

// ---------------- launch ----------------------------------------------------
extern "C" void kernel_launch(void* const* d_in, const int* in_sizes, int n_in,
                              void* d_out, int out_size) {
    InPtrs P;
    for (int l = 0; l < 5; l++) { P.cls[l] = nullptr; P.cnt[l] = nullptr; P.reg[l] = nullptr; }
    bool seen131072 = false, seen32768 = false, seen8192 = false, seen2048 = false;

    for (int i = 0; i < n_in; i++) {
        const float* p = (const float*)d_in[i];
        switch (in_sizes[i]) {
            case 10485760: P.cls[0] = p; break;
            case 2621440:  P.cls[1] = p; break;
            case 655360:   P.cls[2] = p; break;
            case 163840:   P.cls[3] = p; break;
            case 40960:    P.cls[4] = p; break;
            case 524288:   P.reg[0] = p; break;
            case 512:      P.cnt[4] = p; break;
            case 131072:   if (!seen131072) { P.cnt[0] = p; seen131072 = true; } else P.reg[1] = p; break;
            case 32768:    if (!seen32768)  { P.cnt[1] = p; seen32768 = true; }  else P.reg[2] = p; break;
            case 8192:     if (!seen8192)   { P.cnt[2] = p; seen8192 = true; }   else P.reg[3] = p; break;
            case 2048:     if (!seen2048)   { P.cnt[3] = p; seen2048 = true; }   else P.reg[4] = p; break;
            default: break; // batch_imgs unused (shape only)
        }
    }

    static bool attr_set = false;
    if (!attr_set) {
        cudaFuncSetAttribute(k_nms_out, cudaFuncAttributeMaxDynamicSharedMemorySize,
                             MROWS * MSTRIDE * (int)sizeof(unsigned));
        attr_set = true;
    }

    dim3 gdec((NA / 4 + 255) / 256, BATCH);
    k_decode<<<gdec, 256>>>(P);
    k_topk_gather<<<BATCH, 1024>>>();
    k_mask<<<dim3(32, BATCH), 1024>>>();
    k_nms_out<<<BATCH, 1024, MROWS * MSTRIDE * sizeof(unsigned)>>>((float*)d_out);
    (void)out_size;
}